// round 12
// baseline (speedup 1.0000x reference)
#include <cuda_runtime.h>
#include <cuda_bf16.h>
#include <cstdint>

// ============================ problem constants ============================
#define BATCH 4
#define SEQ   1024
#define HID   4096
#define NHEAD 32
#define HDIM  128
#define M_ROWS (BATCH*SEQ)          // 4096
#define QKV_N  (3*HID)              // 12288
#define KDIM   4096
#define HEAD_ELEMS (BATCH*NHEAD*SEQ*HDIM)  // 16,777,216 per part

// ============================ scratch (device globals) =====================
__device__ float g_qkv[3ull * HEAD_ELEMS];                 // [part][b][h][s][d] fp32
__device__ __nv_bfloat16 g_a1hi[(size_t)M_ROWS * KDIM];
__device__ __nv_bfloat16 g_a1lo[(size_t)M_ROWS * KDIM];
__device__ __nv_bfloat16 g_bphi[(size_t)QKV_N * KDIM];
__device__ __nv_bfloat16 g_bplo[(size_t)QKV_N * KDIM];
__device__ __nv_bfloat16 g_bohi[(size_t)HID * KDIM];
__device__ __nv_bfloat16 g_bolo[(size_t)HID * KDIM];
__device__ __nv_bfloat16 g_athi[(size_t)M_ROWS * HID];
__device__ __nv_bfloat16 g_atlo[(size_t)M_ROWS * HID];
// attention operands (bf16 hi/lo)
__device__ __nv_bfloat16 g_qhi[(size_t)HEAD_ELEMS];        // [bh][s][d]
__device__ __nv_bfloat16 g_qlo[(size_t)HEAD_ELEMS];
__device__ __nv_bfloat16 g_khi[(size_t)HEAD_ELEMS];
__device__ __nv_bfloat16 g_klo[(size_t)HEAD_ELEMS];
__device__ __nv_bfloat16 g_vthi[(size_t)HEAD_ELEMS];       // [bh][d][s]
__device__ __nv_bfloat16 g_vtlo[(size_t)HEAD_ELEMS];

// ============================ helpers ======================================
__device__ __forceinline__ uint32_t smem_to_u32(const void* p) {
    uint32_t a;
    asm("{ .reg .u64 t; cvta.to.shared.u64 t, %1; cvt.u32.u64 %0, t; }" : "=r"(a) : "l"(p));
    return a;
}

__device__ __forceinline__ void ldmatrix_x4(uint32_t& r0, uint32_t& r1,
                                            uint32_t& r2, uint32_t& r3, uint32_t addr) {
    asm volatile("ldmatrix.sync.aligned.m8n8.x4.shared.b16 {%0,%1,%2,%3}, [%4];"
                 : "=r"(r0), "=r"(r1), "=r"(r2), "=r"(r3) : "r"(addr));
}

__device__ __forceinline__ void mma_bf16(float* d, const uint32_t* a, uint32_t b0, uint32_t b1) {
    asm volatile(
        "mma.sync.aligned.m16n8k16.row.col.f32.bf16.bf16.f32 "
        "{%0,%1,%2,%3}, {%4,%5,%6,%7}, {%8,%9}, {%0,%1,%2,%3};"
        : "+f"(d[0]), "+f"(d[1]), "+f"(d[2]), "+f"(d[3])
        : "r"(a[0]), "r"(a[1]), "r"(a[2]), "r"(a[3]), "r"(b0), "r"(b1));
}

__device__ __forceinline__ uint32_t pack_bf16x2(float x, float y) {
    __nv_bfloat162 t = __floats2bfloat162_rn(x, y);
    return *(uint32_t*)&t;
}
__device__ __forceinline__ float bf16_res(float x) {
    return x - __bfloat162float(__float2bfloat16(x));
}

// ============================ prep kernels =================================
__global__ void split_kernel(const float* __restrict__ x,
                             __nv_bfloat16* __restrict__ hi,
                             __nv_bfloat16* __restrict__ lo, int n4)
{
    int idx = blockIdx.x * blockDim.x + threadIdx.x;
    if (idx >= n4) return;
    float4 v = ((const float4*)x)[idx];
    __nv_bfloat16 h0 = __float2bfloat16(v.x), h1 = __float2bfloat16(v.y);
    __nv_bfloat16 h2 = __float2bfloat16(v.z), h3 = __float2bfloat16(v.w);
    __nv_bfloat16 l0 = __float2bfloat16(v.x - __bfloat162float(h0));
    __nv_bfloat16 l1 = __float2bfloat16(v.y - __bfloat162float(h1));
    __nv_bfloat16 l2 = __float2bfloat16(v.z - __bfloat162float(h2));
    __nv_bfloat16 l3 = __float2bfloat16(v.w - __bfloat162float(h3));
    __nv_bfloat162* hp = (__nv_bfloat162*)hi;
    __nv_bfloat162* lp = (__nv_bfloat162*)lo;
    hp[idx * 2 + 0] = __nv_bfloat162(h0, h1);
    hp[idx * 2 + 1] = __nv_bfloat162(h2, h3);
    lp[idx * 2 + 0] = __nv_bfloat162(l0, l1);
    lp[idx * 2 + 1] = __nv_bfloat162(l2, l3);
}

__global__ void transpose_split_kernel(const float* __restrict__ W,
                                       __nv_bfloat16* __restrict__ hi,
                                       __nv_bfloat16* __restrict__ lo,
                                       int K, int N)
{
    __shared__ float t[32][33];
    int n0 = blockIdx.x * 32, k0 = blockIdx.y * 32;
    int tx = threadIdx.x, ty = threadIdx.y;   // 32 x 8
#pragma unroll
    for (int j = 0; j < 32; j += 8)
        t[ty + j][tx] = W[(size_t)(k0 + ty + j) * N + n0 + tx];
    __syncthreads();
#pragma unroll
    for (int j = 0; j < 32; j += 8) {
        float v = t[tx][ty + j];
        __nv_bfloat16 h = __float2bfloat16(v);
        __nv_bfloat16 l = __float2bfloat16(v - __bfloat162float(h));
        size_t o = (size_t)(n0 + ty + j) * K + k0 + tx;
        hi[o] = h;
        lo[o] = l;
    }
}

// Per-head transpose+split of V: g_qkv part2 [bh][s][d] -> [bh][d][s] bf16 hi/lo
__global__ void vtrans_kernel(const float* __restrict__ V,
                              __nv_bfloat16* __restrict__ vthi,
                              __nv_bfloat16* __restrict__ vtlo)
{
    __shared__ float t[32][33];
    int d0 = blockIdx.x * 32, s0 = blockIdx.y * 32, bh = blockIdx.z;
    int tx = threadIdx.x, ty = threadIdx.y;   // 32 x 8
    const float* Vh = V + (size_t)bh * SEQ * HDIM;
#pragma unroll
    for (int j = 0; j < 32; j += 8)
        t[ty + j][tx] = Vh[(size_t)(s0 + ty + j) * HDIM + d0 + tx];
    __syncthreads();
    size_t obase = (size_t)bh * HDIM * SEQ;
#pragma unroll
    for (int j = 0; j < 32; j += 8) {
        float v = t[tx][ty + j];
        __nv_bfloat16 h = __float2bfloat16(v);
        __nv_bfloat16 l = __float2bfloat16(v - __bfloat162float(h));
        size_t o = obase + (size_t)(d0 + ty + j) * SEQ + s0 + tx;
        vthi[o] = h;
        vtlo[o] = l;
    }
}

// ============================ HMMA GEMM ====================================
// C[M,N] = (Ahi+Alo)[M,K] @ (Bhi+Blo)^T, fp32 acc, bf16x3 m16n8k16.
// BM=BN=128, BK=64, 256 threads, warps 2(M)x4(N).
// 3-stage cp.async.cg ring, 1 CTA/SM, one __syncthreads per K-tile:
// while computing kt, loads kt+1 and kt+2 are in flight (wait_group 1).
// Compute body identical to R10/R11 (reuse-ordered, 12 LDSM.x4 per k16-step).
#define BK 64
#define KT_STEPS (KDIM / BK)     // 64
#define ARR 18432                // 128 * 144 bytes
#define STAGE (4 * ARR)          // 73728
#define GEMM_SMEM (3 * STAGE)    // 221184

template<int EPI>
__global__ void __launch_bounds__(256, 1)
hmma_gemm_kernel(const __nv_bfloat16* __restrict__ Ahi,
                 const __nv_bfloat16* __restrict__ Alo,
                 const __nv_bfloat16* __restrict__ Bhi,
                 const __nv_bfloat16* __restrict__ Blo,
                 float* __restrict__ C)
{
    extern __shared__ __align__(16) char smem[];
    const uint32_t sbase = smem_to_u32(smem);

    const int tid  = threadIdx.x;
    const int lane = tid & 31;
    const int wid  = tid >> 5;
    const int wm   = wid >> 2;
    const int wn   = wid & 3;
    const int bm   = blockIdx.y * 128;
    const int bn   = blockIdx.x * 128;

    const __nv_bfloat16* garr[4] = {Ahi, Alo, Bhi, Blo};

    const uint32_t a_lane = (uint32_t)(lane & 15) * 144 + (uint32_t)(lane >> 4) * 16;
    const uint32_t b_row  = (uint32_t)((lane & 7) | ((lane >> 4) << 3));
    const uint32_t b_lane = b_row * 144 + (uint32_t)((lane >> 3) & 1) * 16;

    // loader decode: 4096 chunks/stage, 16/thread.
    // id = tid + i*256; arr = i>>2; row = (tid>>3) + (i&3)*32; c = tid&7
    const int r0 = tid >> 3;
    const int c0 = tid & 7;

    auto load_stage = [&](int slot, int k0) {
        uint32_t sb = sbase + (uint32_t)slot * STAGE;
#pragma unroll
        for (int i = 0; i < 16; i++) {
            int arr = i >> 2;
            int row = r0 + (i & 3) * 32;
            int rbase = (arr < 2) ? bm : bn;
            const void* gp = garr[arr] + ((size_t)(rbase + row) * KDIM + k0 + c0 * 8);
            uint32_t so = sb + (uint32_t)(arr * ARR + row * 144 + c0 * 16);
            asm volatile("cp.async.cg.shared.global [%0], [%1], 16;" :: "r"(so), "l"(gp));
        }
        asm volatile("cp.async.commit_group;" ::: "memory");
    };

    float acc[4][4][4];
#pragma unroll
    for (int i = 0; i < 4; i++)
#pragma unroll
        for (int j = 0; j < 4; j++)
#pragma unroll
            for (int r = 0; r < 4; r++) acc[i][j][r] = 0.f;

    load_stage(0, 0);
    load_stage(1, BK);

    int cur = 0;
    for (int kt = 0; kt < KT_STEPS; kt++) {
        if (kt + 1 < KT_STEPS) {
            asm volatile("cp.async.wait_group 1;" ::: "memory");
        } else {
            asm volatile("cp.async.wait_group 0;" ::: "memory");
        }
        __syncthreads();   // tile kt resident; slot (cur+2)%3 no longer being read

        int nslot = cur + 2; if (nslot >= 3) nslot -= 3;
        if (kt + 2 < KT_STEPS) load_stage(nslot, (kt + 2) * BK);

        const uint32_t buf = sbase + (uint32_t)cur * STAGE;
#pragma unroll
        for (int ks = 0; ks < 4; ks++) {
            const uint32_t kb = (uint32_t)ks * 32;

            uint32_t a[4][4], bh[2][4], bl[2][4];
#pragma unroll
            for (int mt = 0; mt < 4; mt++)
                ldmatrix_x4(a[mt][0], a[mt][1], a[mt][2], a[mt][3],
                            buf + (uint32_t)(wm * 64 + mt * 16) * 144 + kb + a_lane);
#pragma unroll
            for (int n2 = 0; n2 < 2; n2++)
                ldmatrix_x4(bh[n2][0], bh[n2][1], bh[n2][2], bh[n2][3],
                            buf + 2u * ARR + (uint32_t)(wn * 32 + n2 * 16) * 144 + kb + b_lane);
#pragma unroll
            for (int n2 = 0; n2 < 2; n2++)
                ldmatrix_x4(bl[n2][0], bl[n2][1], bl[n2][2], bl[n2][3],
                            buf + 3u * ARR + (uint32_t)(wn * 32 + n2 * 16) * 144 + kb + b_lane);

#pragma unroll
            for (int mt = 0; mt < 4; mt++)
#pragma unroll
                for (int nt = 0; nt < 4; nt++) {
                    mma_bf16(acc[mt][nt], a[mt],
                             bh[nt >> 1][(nt & 1) * 2], bh[nt >> 1][(nt & 1) * 2 + 1]);
                    mma_bf16(acc[mt][nt], a[mt],
                             bl[nt >> 1][(nt & 1) * 2], bl[nt >> 1][(nt & 1) * 2 + 1]);
                }

#pragma unroll
            for (int mt = 0; mt < 4; mt++)
                ldmatrix_x4(a[mt][0], a[mt][1], a[mt][2], a[mt][3],
                            buf + ARR + (uint32_t)(wm * 64 + mt * 16) * 144 + kb + a_lane);
#pragma unroll
            for (int mt = 0; mt < 4; mt++)
#pragma unroll
                for (int nt = 0; nt < 4; nt++)
                    mma_bf16(acc[mt][nt], a[mt],
                             bh[nt >> 1][(nt & 1) * 2], bh[nt >> 1][(nt & 1) * 2 + 1]);
        }
        cur = (cur + 1 == 3) ? 0 : cur + 1;
    }

#pragma unroll
    for (int mt = 0; mt < 4; mt++) {
#pragma unroll
        for (int half = 0; half < 2; half++) {
            int row = bm + wm * 64 + mt * 16 + (lane >> 2) + half * 8;
#pragma unroll
            for (int nt = 0; nt < 4; nt++) {
                int col = bn + wn * 32 + nt * 8 + (lane & 3) * 2;
                float v0 = acc[mt][nt][half * 2 + 0];
                float v1 = acc[mt][nt][half * 2 + 1];
                if (EPI == 0) {
                    C[(size_t)row * HID + col]     = v0;
                    C[(size_t)row * HID + col + 1] = v1;
                } else {
                    int b = row >> 10, s = row & 1023;
                    int part = col >> 12;
                    int rem  = col & 4095;
                    int h    = rem >> 7;
                    int d    = rem & 127;
                    size_t idx = ((((size_t)(part * BATCH + b) * NHEAD + h) * SEQ + s) * HDIM) + d;
                    C[idx]     = v0;
                    C[idx + 1] = v1;
                }
            }
        }
    }
}

// ============================ RoPE -> bf16 hi/lo ===========================
__global__ void rope_kernel(const float* __restrict__ qkv,
                            __nv_bfloat16* __restrict__ qhi, __nv_bfloat16* __restrict__ qlo,
                            __nv_bfloat16* __restrict__ khi, __nv_bfloat16* __restrict__ klo)
{
    int s  = blockIdx.x;
    int pb = blockIdx.y;
    int part = pb >> 7;
    int bh   = pb & 127;
    int d    = threadIdx.x;

    float p = (float)s;
    float e = (float)(2 * d) * (1.0f / 128.0f);
    float inv_freq = 1.0f / powf(10000.0f, e);
    float freq = p * inv_freq;
    float c = cosf(freq);
    float sn = sinf(freq);

    size_t base = ((size_t)(part * BATCH * NHEAD + bh) * SEQ + s) * HDIM;
    float x1 = qkv[base + d];
    float x2 = qkv[base + d + 64];
    float y1 = x1 * c - x2 * sn;
    float y2 = x2 * c + x1 * sn;

    __nv_bfloat16* hi = part ? khi : qhi;
    __nv_bfloat16* lo = part ? klo : qlo;
    size_t ob = ((size_t)bh * SEQ + s) * HDIM;
    __nv_bfloat16 h1 = __float2bfloat16(y1);
    __nv_bfloat16 h2 = __float2bfloat16(y2);
    hi[ob + d]      = h1;
    hi[ob + d + 64] = h2;
    lo[ob + d]      = __float2bfloat16(y1 - __bfloat162float(h1));
    lo[ob + d + 64] = __float2bfloat16(y2 - __bfloat162float(h2));
}

// ============================ HMMA flash attention =========================
#define AT_QROW 272
#define AT_VROW 144
#define AT_QHI 0
#define AT_QLO 17408
#define AT_KHI 34816
#define AT_KLO 52224
#define AT_VHI 69632
#define AT_VLO 88064
#define ATTN_SMEM 106496

__global__ void __launch_bounds__(128)
attn_kernel(const __nv_bfloat16* __restrict__ qhi, const __nv_bfloat16* __restrict__ qlo,
            const __nv_bfloat16* __restrict__ khi, const __nv_bfloat16* __restrict__ klo,
            const __nv_bfloat16* __restrict__ vthi, const __nv_bfloat16* __restrict__ vtlo,
            __nv_bfloat16* __restrict__ out_hi, __nv_bfloat16* __restrict__ out_lo)
{
    extern __shared__ __align__(16) char sm[];
    const uint32_t sb = smem_to_u32(sm);

    const int tid  = threadIdx.x;
    const int lane = tid & 31;
    const int w    = tid >> 5;
    const int qt   = blockIdx.x;
    const int bh   = blockIdx.y;
    const int b    = bh >> 5;
    const int h    = bh & 31;
    const int q0   = qt * 64;
    const size_t hoff  = (size_t)bh * SEQ * HDIM;
    const size_t vbase = (size_t)bh * HDIM * SEQ;

    const uint32_t a_lane  = (uint32_t)(lane & 15) * AT_QROW + (uint32_t)(lane >> 4) * 16;
    const uint32_t b_row   = (uint32_t)((lane & 7) | ((lane >> 4) << 3));
    const uint32_t bk_lane = b_row * AT_QROW + (uint32_t)((lane >> 3) & 1) * 16;
    const uint32_t bv_lane = b_row * AT_VROW + (uint32_t)((lane >> 3) & 1) * 16;

    for (int i = tid; i < 2048; i += 128) {
        int arr = i >> 10, rem = i & 1023;
        int r = rem >> 4, c = rem & 15;
        const __nv_bfloat16* src = (arr ? qlo : qhi) + hoff + (size_t)(q0 + r) * HDIM + c * 8;
        uint4 v = *(const uint4*)src;
        *(uint4*)(sm + (arr ? AT_QLO : AT_QHI) + r * AT_QROW + c * 16) = v;
    }

    const int g = lane >> 2;
    const int qq0 = q0 + w * 16 + g;
    const int qq1 = qq0 + 8;
    const float scale = 0.08838834764831845f;

    float oa[16][4];
#pragma unroll
    for (int i = 0; i < 16; i++)
#pragma unroll
        for (int r = 0; r < 4; r++) oa[i][r] = 0.f;
    float m0 = -1e30f, m1 = -1e30f, l0 = 0.f, l1 = 0.f;

    for (int kt = 0; kt <= qt; kt++) {
        const int k0 = kt * 64;
        __syncthreads();
        for (int i = tid; i < 4096; i += 128) {
            if (i < 2048) {
                int arr = i >> 10, rem = i & 1023;
                int r = rem >> 4, c = rem & 15;
                const __nv_bfloat16* src = (arr ? klo : khi) + hoff + (size_t)(k0 + r) * HDIM + c * 8;
                uint4 v = *(const uint4*)src;
                *(uint4*)(sm + (arr ? AT_KLO : AT_KHI) + r * AT_QROW + c * 16) = v;
            } else {
                int i2 = i - 2048;
                int arr = i2 >> 10, rem = i2 & 1023;
                int r = rem >> 3, c = rem & 7;
                const __nv_bfloat16* src = (arr ? vtlo : vthi) + vbase + (size_t)r * SEQ + k0 + c * 8;
                uint4 v = *(const uint4*)src;
                *(uint4*)(sm + (arr ? AT_VLO : AT_VHI) + r * AT_VROW + c * 16) = v;
            }
        }
        __syncthreads();

        float sc[8][4];
#pragma unroll
        for (int j = 0; j < 8; j++)
#pragma unroll
            for (int r = 0; r < 4; r++) sc[j][r] = 0.f;

#pragma unroll
        for (int ks = 0; ks < 8; ks++) {
            const uint32_t kb = (uint32_t)ks * 32;
            uint32_t ah[4], al[4], kh[4][4], kl[4][4];
            ldmatrix_x4(ah[0], ah[1], ah[2], ah[3],
                        sb + AT_QHI + (uint32_t)(w * 16) * AT_QROW + kb + a_lane);
            ldmatrix_x4(al[0], al[1], al[2], al[3],
                        sb + AT_QLO + (uint32_t)(w * 16) * AT_QROW + kb + a_lane);
#pragma unroll
            for (int j2 = 0; j2 < 4; j2++) {
                ldmatrix_x4(kh[j2][0], kh[j2][1], kh[j2][2], kh[j2][3],
                            sb + AT_KHI + (uint32_t)(j2 * 16) * AT_QROW + kb + bk_lane);
                ldmatrix_x4(kl[j2][0], kl[j2][1], kl[j2][2], kl[j2][3],
                            sb + AT_KLO + (uint32_t)(j2 * 16) * AT_QROW + kb + bk_lane);
            }
#pragma unroll
            for (int j = 0; j < 8; j++) {
                uint32_t b0h = kh[j >> 1][(j & 1) * 2], b1h = kh[j >> 1][(j & 1) * 2 + 1];
                uint32_t b0l = kl[j >> 1][(j & 1) * 2], b1l = kl[j >> 1][(j & 1) * 2 + 1];
                mma_bf16(sc[j], ah, b0h, b1h);
                mma_bf16(sc[j], ah, b0l, b1l);
                mma_bf16(sc[j], al, b0h, b1h);
            }
        }

        if (kt == qt) {
#pragma unroll
            for (int j = 0; j < 8; j++) {
                int c0 = k0 + j * 8 + (lane & 3) * 2;
                sc[j][0] = sc[j][0] * scale + ((c0     <= qq0) ? 0.f : -1e9f);
                sc[j][1] = sc[j][1] * scale + ((c0 + 1 <= qq0) ? 0.f : -1e9f);
                sc[j][2] = sc[j][2] * scale + ((c0     <= qq1) ? 0.f : -1e9f);
                sc[j][3] = sc[j][3] * scale + ((c0 + 1 <= qq1) ? 0.f : -1e9f);
            }
        } else {
#pragma unroll
            for (int j = 0; j < 8; j++)
#pragma unroll
                for (int r = 0; r < 4; r++) sc[j][r] *= scale;
        }

        float mx0 = -1e30f, mx1 = -1e30f;
#pragma unroll
        for (int j = 0; j < 8; j++) {
            mx0 = fmaxf(mx0, fmaxf(sc[j][0], sc[j][1]));
            mx1 = fmaxf(mx1, fmaxf(sc[j][2], sc[j][3]));
        }
        mx0 = fmaxf(mx0, __shfl_xor_sync(0xffffffffu, mx0, 1));
        mx0 = fmaxf(mx0, __shfl_xor_sync(0xffffffffu, mx0, 2));
        mx1 = fmaxf(mx1, __shfl_xor_sync(0xffffffffu, mx1, 1));
        mx1 = fmaxf(mx1, __shfl_xor_sync(0xffffffffu, mx1, 2));
        float mn0 = fmaxf(m0, mx0), mn1 = fmaxf(m1, mx1);
        float al0 = __expf(m0 - mn0), al1 = __expf(m1 - mn1);

        float s0 = 0.f, s1 = 0.f;
#pragma unroll
        for (int j = 0; j < 8; j++) {
            sc[j][0] = __expf(sc[j][0] - mn0); s0 += sc[j][0];
            sc[j][1] = __expf(sc[j][1] - mn0); s0 += sc[j][1];
            sc[j][2] = __expf(sc[j][2] - mn1); s1 += sc[j][2];
            sc[j][3] = __expf(sc[j][3] - mn1); s1 += sc[j][3];
        }
        s0 += __shfl_xor_sync(0xffffffffu, s0, 1);
        s0 += __shfl_xor_sync(0xffffffffu, s0, 2);
        s1 += __shfl_xor_sync(0xffffffffu, s1, 1);
        s1 += __shfl_xor_sync(0xffffffffu, s1, 2);
        l0 = l0 * al0 + s0; m0 = mn0;
        l1 = l1 * al1 + s1; m1 = mn1;

#pragma unroll
        for (int i = 0; i < 16; i++) {
            oa[i][0] *= al0; oa[i][1] *= al0;
            oa[i][2] *= al1; oa[i][3] *= al1;
        }

        uint32_t pfh[4][4], pfl[4][4];
#pragma unroll
        for (int t = 0; t < 4; t++) {
            int j = 2 * t;
            pfh[t][0] = pack_bf16x2(sc[j][0],     sc[j][1]);
            pfh[t][1] = pack_bf16x2(sc[j][2],     sc[j][3]);
            pfh[t][2] = pack_bf16x2(sc[j + 1][0], sc[j + 1][1]);
            pfh[t][3] = pack_bf16x2(sc[j + 1][2], sc[j + 1][3]);
            pfl[t][0] = pack_bf16x2(bf16_res(sc[j][0]),     bf16_res(sc[j][1]));
            pfl[t][1] = pack_bf16x2(bf16_res(sc[j][2]),     bf16_res(sc[j][3]));
            pfl[t][2] = pack_bf16x2(bf16_res(sc[j + 1][0]), bf16_res(sc[j + 1][1]));
            pfl[t][3] = pack_bf16x2(bf16_res(sc[j + 1][2]), bf16_res(sc[j + 1][3]));
        }

#pragma unroll
        for (int t = 0; t < 4; t++) {
            const uint32_t kb = (uint32_t)t * 32;
#pragma unroll
            for (int n2 = 0; n2 < 8; n2++) {
                uint32_t vh[4], vl[4];
                ldmatrix_x4(vh[0], vh[1], vh[2], vh[3],
                            sb + AT_VHI + (uint32_t)(n2 * 16) * AT_VROW + kb + bv_lane);
                ldmatrix_x4(vl[0], vl[1], vl[2], vl[3],
                            sb + AT_VLO + (uint32_t)(n2 * 16) * AT_VROW + kb + bv_lane);
#pragma unroll
                for (int q = 0; q < 2; q++) {
                    int nt = n2 * 2 + q;
                    mma_bf16(oa[nt], pfh[t], vh[q * 2], vh[q * 2 + 1]);
                    mma_bf16(oa[nt], pfh[t], vl[q * 2], vl[q * 2 + 1]);
                    mma_bf16(oa[nt], pfl[t], vh[q * 2], vh[q * 2 + 1]);
                }
            }
        }
    }

    float il0 = 1.f / l0, il1 = 1.f / l1;
    size_t base0 = ((size_t)(b * SEQ + qq0)) * HID + (size_t)h * HDIM;
    size_t base1 = ((size_t)(b * SEQ + qq1)) * HID + (size_t)h * HDIM;
#pragma unroll
    for (int nt = 0; nt < 16; nt++) {
        int d = nt * 8 + (lane & 3) * 2;
        float v00 = oa[nt][0] * il0, v01 = oa[nt][1] * il0;
        float v10 = oa[nt][2] * il1, v11 = oa[nt][3] * il1;
        *(uint32_t*)(out_hi + base0 + d) = pack_bf16x2(v00, v01);
        *(uint32_t*)(out_lo + base0 + d) = pack_bf16x2(bf16_res(v00), bf16_res(v01));
        *(uint32_t*)(out_hi + base1 + d) = pack_bf16x2(v10, v11);
        *(uint32_t*)(out_lo + base1 + d) = pack_bf16x2(bf16_res(v10), bf16_res(v11));
    }
}

// ============================ launch =======================================
extern "C" void kernel_launch(void* const* d_in, const int* in_sizes, int n_in,
                              void* d_out, int out_size)
{
    const float* hidden = (const float*)d_in[0];
    const float* Wp     = (const float*)d_in[1];
    const float* Wo     = (const float*)d_in[2];
    float* out = (float*)d_out;

    float *qkv = nullptr;
    __nv_bfloat16 *a1hi, *a1lo, *bphi, *bplo, *bohi, *bolo, *athi, *atlo;
    __nv_bfloat16 *qhi, *qlo, *khi, *klo, *vthi, *vtlo;
    cudaGetSymbolAddress((void**)&qkv,  g_qkv);
    cudaGetSymbolAddress((void**)&a1hi, g_a1hi);
    cudaGetSymbolAddress((void**)&a1lo, g_a1lo);
    cudaGetSymbolAddress((void**)&bphi, g_bphi);
    cudaGetSymbolAddress((void**)&bplo, g_bplo);
    cudaGetSymbolAddress((void**)&bohi, g_bohi);
    cudaGetSymbolAddress((void**)&bolo, g_bolo);
    cudaGetSymbolAddress((void**)&athi, g_athi);
    cudaGetSymbolAddress((void**)&atlo, g_atlo);
    cudaGetSymbolAddress((void**)&qhi,  g_qhi);
    cudaGetSymbolAddress((void**)&qlo,  g_qlo);
    cudaGetSymbolAddress((void**)&khi,  g_khi);
    cudaGetSymbolAddress((void**)&klo,  g_klo);
    cudaGetSymbolAddress((void**)&vthi, g_vthi);
    cudaGetSymbolAddress((void**)&vtlo, g_vtlo);

    // Prep: split hidden; transpose+split weights
    split_kernel<<<(M_ROWS * KDIM / 4 + 255) / 256, 256>>>(hidden, a1hi, a1lo, M_ROWS * KDIM / 4);
    transpose_split_kernel<<<dim3(QKV_N / 32, KDIM / 32), dim3(32, 8)>>>(Wp, bphi, bplo, KDIM, QKV_N);
    transpose_split_kernel<<<dim3(HID  / 32, KDIM / 32), dim3(32, 8)>>>(Wo, bohi, bolo, KDIM, HID);

    cudaFuncSetAttribute(hmma_gemm_kernel<0>, cudaFuncAttributeMaxDynamicSharedMemorySize, GEMM_SMEM);
    cudaFuncSetAttribute(hmma_gemm_kernel<1>, cudaFuncAttributeMaxDynamicSharedMemorySize, GEMM_SMEM);
    cudaFuncSetAttribute(attn_kernel, cudaFuncAttributeMaxDynamicSharedMemorySize, ATTN_SMEM);

    // GEMM1: QKV projection -> g_qkv head-major fp32
    hmma_gemm_kernel<1><<<dim3(QKV_N / 128, M_ROWS / 128), 256, GEMM_SMEM>>>(
        a1hi, a1lo, bphi, bplo, qkv);

    // RoPE -> Q/K bf16 hi/lo; V -> V^T bf16 hi/lo
    rope_kernel<<<dim3(SEQ, 2 * BATCH * NHEAD), 64>>>(qkv, qhi, qlo, khi, klo);
    vtrans_kernel<<<dim3(HDIM / 32, SEQ / 32, BATCH * NHEAD), dim3(32, 8)>>>(
        qkv + 2ull * HEAD_ELEMS, vthi, vtlo);

    // Flash attention (HMMA) -> bf16 hi/lo
    attn_kernel<<<dim3(SEQ / 64, BATCH * NHEAD), 128, ATTN_SMEM>>>(
        qhi, qlo, khi, klo, vthi, vtlo, athi, atlo);

    // GEMM2: output projection
    hmma_gemm_kernel<0><<<dim3(HID / 128, M_ROWS / 128), 256, GEMM_SMEM>>>(
        athi, atlo, bohi, bolo, out);
}

// round 13
// speedup vs baseline: 1.1355x; 1.1355x over previous
#include <cuda_runtime.h>
#include <cuda_bf16.h>
#include <cstdint>

// ============================ problem constants ============================
#define BATCH 4
#define SEQ   1024
#define HID   4096
#define NHEAD 32
#define HDIM  128
#define M_ROWS (BATCH*SEQ)          // 4096
#define QKV_N  (3*HID)              // 12288
#define KDIM   4096
#define HEAD_ELEMS (BATCH*NHEAD*SEQ*HDIM)  // 16,777,216 per part

// ============================ scratch (device globals) =====================
__device__ float g_qkv[3ull * HEAD_ELEMS];                 // [part][b][h][s][d] fp32
__device__ __nv_bfloat16 g_a1hi[(size_t)M_ROWS * KDIM];
__device__ __nv_bfloat16 g_a1lo[(size_t)M_ROWS * KDIM];
__device__ __nv_bfloat16 g_bphi[(size_t)QKV_N * KDIM];
__device__ __nv_bfloat16 g_bplo[(size_t)QKV_N * KDIM];
__device__ __nv_bfloat16 g_bohi[(size_t)HID * KDIM];
__device__ __nv_bfloat16 g_bolo[(size_t)HID * KDIM];
__device__ __nv_bfloat16 g_athi[(size_t)M_ROWS * HID];
__device__ __nv_bfloat16 g_atlo[(size_t)M_ROWS * HID];
// attention operands (bf16 hi/lo)
__device__ __nv_bfloat16 g_qhi[(size_t)HEAD_ELEMS];        // [bh][s][d]
__device__ __nv_bfloat16 g_qlo[(size_t)HEAD_ELEMS];
__device__ __nv_bfloat16 g_khi[(size_t)HEAD_ELEMS];
__device__ __nv_bfloat16 g_klo[(size_t)HEAD_ELEMS];
__device__ __nv_bfloat16 g_vthi[(size_t)HEAD_ELEMS];       // [bh][d][s]
__device__ __nv_bfloat16 g_vtlo[(size_t)HEAD_ELEMS];

// ============================ helpers ======================================
__device__ __forceinline__ uint32_t smem_to_u32(const void* p) {
    uint32_t a;
    asm("{ .reg .u64 t; cvta.to.shared.u64 t, %1; cvt.u32.u64 %0, t; }" : "=r"(a) : "l"(p));
    return a;
}

__device__ __forceinline__ void ldmatrix_x4(uint32_t& r0, uint32_t& r1,
                                            uint32_t& r2, uint32_t& r3, uint32_t addr) {
    asm volatile("ldmatrix.sync.aligned.m8n8.x4.shared.b16 {%0,%1,%2,%3}, [%4];"
                 : "=r"(r0), "=r"(r1), "=r"(r2), "=r"(r3) : "r"(addr));
}

__device__ __forceinline__ void mma_bf16(float* d, const uint32_t* a, uint32_t b0, uint32_t b1) {
    asm volatile(
        "mma.sync.aligned.m16n8k16.row.col.f32.bf16.bf16.f32 "
        "{%0,%1,%2,%3}, {%4,%5,%6,%7}, {%8,%9}, {%0,%1,%2,%3};"
        : "+f"(d[0]), "+f"(d[1]), "+f"(d[2]), "+f"(d[3])
        : "r"(a[0]), "r"(a[1]), "r"(a[2]), "r"(a[3]), "r"(b0), "r"(b1));
}

__device__ __forceinline__ uint32_t pack_bf16x2(float x, float y) {
    __nv_bfloat162 t = __floats2bfloat162_rn(x, y);
    return *(uint32_t*)&t;
}
__device__ __forceinline__ float bf16_res(float x) {
    return x - __bfloat162float(__float2bfloat16(x));
}

// ============================ prep kernels =================================
__global__ void split_kernel(const float* __restrict__ x,
                             __nv_bfloat16* __restrict__ hi,
                             __nv_bfloat16* __restrict__ lo, int n4)
{
    int idx = blockIdx.x * blockDim.x + threadIdx.x;
    if (idx >= n4) return;
    float4 v = ((const float4*)x)[idx];
    __nv_bfloat16 h0 = __float2bfloat16(v.x), h1 = __float2bfloat16(v.y);
    __nv_bfloat16 h2 = __float2bfloat16(v.z), h3 = __float2bfloat16(v.w);
    __nv_bfloat16 l0 = __float2bfloat16(v.x - __bfloat162float(h0));
    __nv_bfloat16 l1 = __float2bfloat16(v.y - __bfloat162float(h1));
    __nv_bfloat16 l2 = __float2bfloat16(v.z - __bfloat162float(h2));
    __nv_bfloat16 l3 = __float2bfloat16(v.w - __bfloat162float(h3));
    __nv_bfloat162* hp = (__nv_bfloat162*)hi;
    __nv_bfloat162* lp = (__nv_bfloat162*)lo;
    hp[idx * 2 + 0] = __nv_bfloat162(h0, h1);
    hp[idx * 2 + 1] = __nv_bfloat162(h2, h3);
    lp[idx * 2 + 0] = __nv_bfloat162(l0, l1);
    lp[idx * 2 + 1] = __nv_bfloat162(l2, l3);
}

__global__ void transpose_split_kernel(const float* __restrict__ W,
                                       __nv_bfloat16* __restrict__ hi,
                                       __nv_bfloat16* __restrict__ lo,
                                       int K, int N)
{
    __shared__ float t[32][33];
    int n0 = blockIdx.x * 32, k0 = blockIdx.y * 32;
    int tx = threadIdx.x, ty = threadIdx.y;   // 32 x 8
#pragma unroll
    for (int j = 0; j < 32; j += 8)
        t[ty + j][tx] = W[(size_t)(k0 + ty + j) * N + n0 + tx];
    __syncthreads();
#pragma unroll
    for (int j = 0; j < 32; j += 8) {
        float v = t[tx][ty + j];
        __nv_bfloat16 h = __float2bfloat16(v);
        __nv_bfloat16 l = __float2bfloat16(v - __bfloat162float(h));
        size_t o = (size_t)(n0 + ty + j) * K + k0 + tx;
        hi[o] = h;
        lo[o] = l;
    }
}

// Per-head transpose+split of V: g_qkv part2 [bh][s][d] -> [bh][d][s] bf16 hi/lo
__global__ void vtrans_kernel(const float* __restrict__ V,
                              __nv_bfloat16* __restrict__ vthi,
                              __nv_bfloat16* __restrict__ vtlo)
{
    __shared__ float t[32][33];
    int d0 = blockIdx.x * 32, s0 = blockIdx.y * 32, bh = blockIdx.z;
    int tx = threadIdx.x, ty = threadIdx.y;   // 32 x 8
    const float* Vh = V + (size_t)bh * SEQ * HDIM;
#pragma unroll
    for (int j = 0; j < 32; j += 8)
        t[ty + j][tx] = Vh[(size_t)(s0 + ty + j) * HDIM + d0 + tx];
    __syncthreads();
    size_t obase = (size_t)bh * HDIM * SEQ;
#pragma unroll
    for (int j = 0; j < 32; j += 8) {
        float v = t[tx][ty + j];
        __nv_bfloat16 h = __float2bfloat16(v);
        __nv_bfloat16 l = __float2bfloat16(v - __bfloat162float(h));
        size_t o = obase + (size_t)(d0 + ty + j) * SEQ + s0 + tx;
        vthi[o] = h;
        vtlo[o] = l;
    }
}

// ============================ HMMA GEMM (R11 config, reverted) =============
#define BK 64
#define KT_STEPS (KDIM / BK)     // 64
#define ARR 18432                // 128 * 144 bytes
#define GEMM_SMEM (4 * ARR)      // 73728

template<int EPI>
__global__ void __launch_bounds__(256, 2)
hmma_gemm_kernel(const __nv_bfloat16* __restrict__ Ahi,
                 const __nv_bfloat16* __restrict__ Alo,
                 const __nv_bfloat16* __restrict__ Bhi,
                 const __nv_bfloat16* __restrict__ Blo,
                 float* __restrict__ C)
{
    extern __shared__ __align__(16) char smem[];
    const uint32_t sbase = smem_to_u32(smem);

    const int tid  = threadIdx.x;
    const int lane = tid & 31;
    const int wid  = tid >> 5;
    const int wm   = wid >> 2;
    const int wn   = wid & 3;
    const int bm   = blockIdx.y * 128;
    const int bn   = blockIdx.x * 128;

    const __nv_bfloat16* garr[4] = {Ahi, Alo, Bhi, Blo};

    const uint32_t a_lane = (uint32_t)(lane & 15) * 144 + (uint32_t)(lane >> 4) * 16;
    const uint32_t b_row  = (uint32_t)((lane & 7) | ((lane >> 4) << 3));
    const uint32_t b_lane = b_row * 144 + (uint32_t)((lane >> 3) & 1) * 16;

    float acc[4][4][4];
#pragma unroll
    for (int i = 0; i < 4; i++)
#pragma unroll
        for (int j = 0; j < 4; j++)
#pragma unroll
            for (int r = 0; r < 4; r++) acc[i][j][r] = 0.f;

    for (int kt = 0; kt < KT_STEPS; kt++) {
        const int k0 = kt * BK;
        __syncthreads();
#pragma unroll
        for (int i = 0; i < 16; i++) {
            int arr  = i >> 2;
            int rem  = ((i & 3) << 8) + tid;
            int row  = rem >> 3;
            int part = rem & 7;
            int rbase = (arr < 2) ? bm : bn;
            const uint4* gp = (const uint4*)(garr[arr] + ((size_t)(rbase + row) * KDIM + k0 + part * 8));
            uint4 v = *gp;
            *(uint4*)(smem + arr * ARR + row * 144 + part * 16) = v;
        }
        __syncthreads();

#pragma unroll
        for (int ks = 0; ks < 4; ks++) {
            const uint32_t kb = (uint32_t)ks * 32;

            uint32_t a[4][4], bh[2][4], bl[2][4];
#pragma unroll
            for (int mt = 0; mt < 4; mt++)
                ldmatrix_x4(a[mt][0], a[mt][1], a[mt][2], a[mt][3],
                            sbase + (uint32_t)(wm * 64 + mt * 16) * 144 + kb + a_lane);
#pragma unroll
            for (int n2 = 0; n2 < 2; n2++)
                ldmatrix_x4(bh[n2][0], bh[n2][1], bh[n2][2], bh[n2][3],
                            sbase + 2u * ARR + (uint32_t)(wn * 32 + n2 * 16) * 144 + kb + b_lane);
#pragma unroll
            for (int n2 = 0; n2 < 2; n2++)
                ldmatrix_x4(bl[n2][0], bl[n2][1], bl[n2][2], bl[n2][3],
                            sbase + 3u * ARR + (uint32_t)(wn * 32 + n2 * 16) * 144 + kb + b_lane);

#pragma unroll
            for (int mt = 0; mt < 4; mt++)
#pragma unroll
                for (int nt = 0; nt < 4; nt++) {
                    mma_bf16(acc[mt][nt], a[mt],
                             bh[nt >> 1][(nt & 1) * 2], bh[nt >> 1][(nt & 1) * 2 + 1]);
                    mma_bf16(acc[mt][nt], a[mt],
                             bl[nt >> 1][(nt & 1) * 2], bl[nt >> 1][(nt & 1) * 2 + 1]);
                }

#pragma unroll
            for (int mt = 0; mt < 4; mt++)
                ldmatrix_x4(a[mt][0], a[mt][1], a[mt][2], a[mt][3],
                            sbase + ARR + (uint32_t)(wm * 64 + mt * 16) * 144 + kb + a_lane);
#pragma unroll
            for (int mt = 0; mt < 4; mt++)
#pragma unroll
                for (int nt = 0; nt < 4; nt++)
                    mma_bf16(acc[mt][nt], a[mt],
                             bh[nt >> 1][(nt & 1) * 2], bh[nt >> 1][(nt & 1) * 2 + 1]);
        }
    }

#pragma unroll
    for (int mt = 0; mt < 4; mt++) {
#pragma unroll
        for (int half = 0; half < 2; half++) {
            int row = bm + wm * 64 + mt * 16 + (lane >> 2) + half * 8;
#pragma unroll
            for (int nt = 0; nt < 4; nt++) {
                int col = bn + wn * 32 + nt * 8 + (lane & 3) * 2;
                float v0 = acc[mt][nt][half * 2 + 0];
                float v1 = acc[mt][nt][half * 2 + 1];
                if (EPI == 0) {
                    C[(size_t)row * HID + col]     = v0;
                    C[(size_t)row * HID + col + 1] = v1;
                } else {
                    int b = row >> 10, s = row & 1023;
                    int part = col >> 12;
                    int rem  = col & 4095;
                    int h    = rem >> 7;
                    int d    = rem & 127;
                    size_t idx = ((((size_t)(part * BATCH + b) * NHEAD + h) * SEQ + s) * HDIM) + d;
                    C[idx]     = v0;
                    C[idx + 1] = v1;
                }
            }
        }
    }
}

// ============================ RoPE -> bf16 hi/lo ===========================
__global__ void rope_kernel(const float* __restrict__ qkv,
                            __nv_bfloat16* __restrict__ qhi, __nv_bfloat16* __restrict__ qlo,
                            __nv_bfloat16* __restrict__ khi, __nv_bfloat16* __restrict__ klo)
{
    int s  = blockIdx.x;
    int pb = blockIdx.y;
    int part = pb >> 7;
    int bh   = pb & 127;
    int d    = threadIdx.x;

    float p = (float)s;
    float e = (float)(2 * d) * (1.0f / 128.0f);
    float inv_freq = 1.0f / powf(10000.0f, e);
    float freq = p * inv_freq;
    float c = cosf(freq);
    float sn = sinf(freq);

    size_t base = ((size_t)(part * BATCH * NHEAD + bh) * SEQ + s) * HDIM;
    float x1 = qkv[base + d];
    float x2 = qkv[base + d + 64];
    float y1 = x1 * c - x2 * sn;
    float y2 = x2 * c + x1 * sn;

    __nv_bfloat16* hi = part ? khi : qhi;
    __nv_bfloat16* lo = part ? klo : qlo;
    size_t ob = ((size_t)bh * SEQ + s) * HDIM;
    __nv_bfloat16 h1 = __float2bfloat16(y1);
    __nv_bfloat16 h2 = __float2bfloat16(y2);
    hi[ob + d]      = h1;
    hi[ob + d + 64] = h2;
    lo[ob + d]      = __float2bfloat16(y1 - __bfloat162float(h1));
    lo[ob + d + 64] = __float2bfloat16(y2 - __bfloat162float(h2));
}

// ============================ HMMA flash attention =========================
// 256 threads (8 warps), BM=128, BN=64, D=128. Warp w owns q rows [w*16,w*16+16).
// Fully-masked tiles are skipped per-warp (barriers still executed by all).
#define AT_QROW 272
#define AT_VROW 144
#define AT_QHI 0
#define AT_QLO 34816
#define AT_KHI 69632
#define AT_KLO 87040
#define AT_VHI 104448
#define AT_VLO 122880
#define ATTN_SMEM 141312

__global__ void __launch_bounds__(256, 1)
attn_kernel(const __nv_bfloat16* __restrict__ qhi, const __nv_bfloat16* __restrict__ qlo,
            const __nv_bfloat16* __restrict__ khi, const __nv_bfloat16* __restrict__ klo,
            const __nv_bfloat16* __restrict__ vthi, const __nv_bfloat16* __restrict__ vtlo,
            __nv_bfloat16* __restrict__ out_hi, __nv_bfloat16* __restrict__ out_lo)
{
    extern __shared__ __align__(16) char sm[];
    const uint32_t sb = smem_to_u32(sm);

    const int tid  = threadIdx.x;
    const int lane = tid & 31;
    const int w    = tid >> 5;         // 0..7
    const int bh   = blockIdx.y;
    const int b    = bh >> 5;
    const int h    = bh & 31;
    const int q0   = blockIdx.x * 128;
    const size_t hoff  = (size_t)bh * SEQ * HDIM;
    const size_t vbase = (size_t)bh * HDIM * SEQ;

    const uint32_t a_lane  = (uint32_t)(lane & 15) * AT_QROW + (uint32_t)(lane >> 4) * 16;
    const uint32_t b_row   = (uint32_t)((lane & 7) | ((lane >> 4) << 3));
    const uint32_t bk_lane = b_row * AT_QROW + (uint32_t)((lane >> 3) & 1) * 16;
    const uint32_t bv_lane = b_row * AT_VROW + (uint32_t)((lane >> 3) & 1) * 16;

    // ---- load Q hi/lo (128 rows x 128 bf16, 272B rows) ----
    for (int i = tid; i < 4096; i += 256) {
        int arr = i >> 11, rem = i & 2047;
        int r = rem >> 4, c = rem & 15;
        const __nv_bfloat16* src = (arr ? qlo : qhi) + hoff + (size_t)(q0 + r) * HDIM + c * 8;
        uint4 v = *(const uint4*)src;
        *(uint4*)(sm + (arr ? AT_QLO : AT_QHI) + r * AT_QROW + c * 16) = v;
    }

    const int g = lane >> 2;
    const int qq0 = q0 + w * 16 + g;   // rows handled by this thread
    const int qq1 = qq0 + 8;
    const int wrow_lo = q0 + w * 16;   // warp's min row
    const int wrow_hi = wrow_lo + 15;  // warp's max row
    const float scale = 0.08838834764831845f;

    float oa[16][4];
#pragma unroll
    for (int i = 0; i < 16; i++)
#pragma unroll
        for (int r = 0; r < 4; r++) oa[i][r] = 0.f;
    float m0 = -1e30f, m1 = -1e30f, l0 = 0.f, l1 = 0.f;

    const int ktmax = 2 * blockIdx.x + 1;
    for (int kt = 0; kt <= ktmax; kt++) {
        const int k0 = kt * 64;
        __syncthreads();
        // ---- load K hi/lo (64x128) + Vt hi/lo (128x64) ----
        for (int i = tid; i < 4096; i += 256) {
            if (i < 2048) {
                int arr = i >> 10, rem = i & 1023;
                int r = rem >> 4, c = rem & 15;
                const __nv_bfloat16* src = (arr ? klo : khi) + hoff + (size_t)(k0 + r) * HDIM + c * 8;
                uint4 v = *(const uint4*)src;
                *(uint4*)(sm + (arr ? AT_KLO : AT_KHI) + r * AT_QROW + c * 16) = v;
            } else {
                int i2 = i - 2048;
                int arr = i2 >> 10, rem = i2 & 1023;
                int r = rem >> 3, c = rem & 7;
                const __nv_bfloat16* src = (arr ? vtlo : vthi) + vbase + (size_t)r * SEQ + k0 + c * 8;
                uint4 v = *(const uint4*)src;
                *(uint4*)(sm + (arr ? AT_VLO : AT_VHI) + r * AT_VROW + c * 16) = v;
            }
        }
        __syncthreads();

        // skip fully-masked tile for this warp (no row >= k0)
        if (k0 > wrow_hi) continue;

        // ---- S = QK^T (bf16x3) ----
        float sc[8][4];
#pragma unroll
        for (int j = 0; j < 8; j++)
#pragma unroll
            for (int r = 0; r < 4; r++) sc[j][r] = 0.f;

#pragma unroll
        for (int ks = 0; ks < 8; ks++) {
            const uint32_t kb = (uint32_t)ks * 32;
            uint32_t ah[4], al[4], kh[4][4], kl[4][4];
            ldmatrix_x4(ah[0], ah[1], ah[2], ah[3],
                        sb + AT_QHI + (uint32_t)(w * 16) * AT_QROW + kb + a_lane);
            ldmatrix_x4(al[0], al[1], al[2], al[3],
                        sb + AT_QLO + (uint32_t)(w * 16) * AT_QROW + kb + a_lane);
#pragma unroll
            for (int j2 = 0; j2 < 4; j2++) {
                ldmatrix_x4(kh[j2][0], kh[j2][1], kh[j2][2], kh[j2][3],
                            sb + AT_KHI + (uint32_t)(j2 * 16) * AT_QROW + kb + bk_lane);
                ldmatrix_x4(kl[j2][0], kl[j2][1], kl[j2][2], kl[j2][3],
                            sb + AT_KLO + (uint32_t)(j2 * 16) * AT_QROW + kb + bk_lane);
            }
#pragma unroll
            for (int j = 0; j < 8; j++) {
                uint32_t b0h = kh[j >> 1][(j & 1) * 2], b1h = kh[j >> 1][(j & 1) * 2 + 1];
                uint32_t b0l = kl[j >> 1][(j & 1) * 2], b1l = kl[j >> 1][(j & 1) * 2 + 1];
                mma_bf16(sc[j], ah, b0h, b1h);
                mma_bf16(sc[j], ah, b0l, b1l);
                mma_bf16(sc[j], al, b0h, b1h);
            }
        }

        // ---- scale (+ causal mask when tile overlaps this warp's diagonal) ----
        if (k0 + 63 > wrow_lo) {
#pragma unroll
            for (int j = 0; j < 8; j++) {
                int c0 = k0 + j * 8 + (lane & 3) * 2;
                sc[j][0] = sc[j][0] * scale + ((c0     <= qq0) ? 0.f : -1e9f);
                sc[j][1] = sc[j][1] * scale + ((c0 + 1 <= qq0) ? 0.f : -1e9f);
                sc[j][2] = sc[j][2] * scale + ((c0     <= qq1) ? 0.f : -1e9f);
                sc[j][3] = sc[j][3] * scale + ((c0 + 1 <= qq1) ? 0.f : -1e9f);
            }
        } else {
#pragma unroll
            for (int j = 0; j < 8; j++)
#pragma unroll
                for (int r = 0; r < 4; r++) sc[j][r] *= scale;
        }

        // ---- online softmax ----
        float mx0 = -1e30f, mx1 = -1e30f;
#pragma unroll
        for (int j = 0; j < 8; j++) {
            mx0 = fmaxf(mx0, fmaxf(sc[j][0], sc[j][1]));
            mx1 = fmaxf(mx1, fmaxf(sc[j][2], sc[j][3]));
        }
        mx0 = fmaxf(mx0, __shfl_xor_sync(0xffffffffu, mx0, 1));
        mx0 = fmaxf(mx0, __shfl_xor_sync(0xffffffffu, mx0, 2));
        mx1 = fmaxf(mx1, __shfl_xor_sync(0xffffffffu, mx1, 1));
        mx1 = fmaxf(mx1, __shfl_xor_sync(0xffffffffu, mx1, 2));
        float mn0 = fmaxf(m0, mx0), mn1 = fmaxf(m1, mx1);
        float al0 = __expf(m0 - mn0), al1 = __expf(m1 - mn1);

        float s0 = 0.f, s1 = 0.f;
#pragma unroll
        for (int j = 0; j < 8; j++) {
            sc[j][0] = __expf(sc[j][0] - mn0); s0 += sc[j][0];
            sc[j][1] = __expf(sc[j][1] - mn0); s0 += sc[j][1];
            sc[j][2] = __expf(sc[j][2] - mn1); s1 += sc[j][2];
            sc[j][3] = __expf(sc[j][3] - mn1); s1 += sc[j][3];
        }
        s0 += __shfl_xor_sync(0xffffffffu, s0, 1);
        s0 += __shfl_xor_sync(0xffffffffu, s0, 2);
        s1 += __shfl_xor_sync(0xffffffffu, s1, 1);
        s1 += __shfl_xor_sync(0xffffffffu, s1, 2);
        l0 = l0 * al0 + s0; m0 = mn0;
        l1 = l1 * al1 + s1; m1 = mn1;

#pragma unroll
        for (int i = 0; i < 16; i++) {
            oa[i][0] *= al0; oa[i][1] *= al0;
            oa[i][2] *= al1; oa[i][3] *= al1;
        }

        // ---- P -> A fragments (hi + residual lo) ----
        uint32_t pfh[4][4], pfl[4][4];
#pragma unroll
        for (int t = 0; t < 4; t++) {
            int j = 2 * t;
            pfh[t][0] = pack_bf16x2(sc[j][0],     sc[j][1]);
            pfh[t][1] = pack_bf16x2(sc[j][2],     sc[j][3]);
            pfh[t][2] = pack_bf16x2(sc[j + 1][0], sc[j + 1][1]);
            pfh[t][3] = pack_bf16x2(sc[j + 1][2], sc[j + 1][3]);
            pfl[t][0] = pack_bf16x2(bf16_res(sc[j][0]),     bf16_res(sc[j][1]));
            pfl[t][1] = pack_bf16x2(bf16_res(sc[j][2]),     bf16_res(sc[j][3]));
            pfl[t][2] = pack_bf16x2(bf16_res(sc[j + 1][0]), bf16_res(sc[j + 1][1]));
            pfl[t][3] = pack_bf16x2(bf16_res(sc[j + 1][2]), bf16_res(sc[j + 1][3]));
        }

        // ---- O += P @ V (bf16x3) ----
#pragma unroll
        for (int t = 0; t < 4; t++) {
            const uint32_t kb = (uint32_t)t * 32;
#pragma unroll
            for (int n2 = 0; n2 < 8; n2++) {
                uint32_t vh[4], vl[4];
                ldmatrix_x4(vh[0], vh[1], vh[2], vh[3],
                            sb + AT_VHI + (uint32_t)(n2 * 16) * AT_VROW + kb + bv_lane);
                ldmatrix_x4(vl[0], vl[1], vl[2], vl[3],
                            sb + AT_VLO + (uint32_t)(n2 * 16) * AT_VROW + kb + bv_lane);
#pragma unroll
                for (int q = 0; q < 2; q++) {
                    int nt = n2 * 2 + q;
                    mma_bf16(oa[nt], pfh[t], vh[q * 2], vh[q * 2 + 1]);
                    mma_bf16(oa[nt], pfh[t], vl[q * 2], vl[q * 2 + 1]);
                    mma_bf16(oa[nt], pfl[t], vh[q * 2], vh[q * 2 + 1]);
                }
            }
        }
    }

    // ---- epilogue ----
    float il0 = 1.f / l0, il1 = 1.f / l1;
    size_t base0 = ((size_t)(b * SEQ + qq0)) * HID + (size_t)h * HDIM;
    size_t base1 = ((size_t)(b * SEQ + qq1)) * HID + (size_t)h * HDIM;
#pragma unroll
    for (int nt = 0; nt < 16; nt++) {
        int d = nt * 8 + (lane & 3) * 2;
        float v00 = oa[nt][0] * il0, v01 = oa[nt][1] * il0;
        float v10 = oa[nt][2] * il1, v11 = oa[nt][3] * il1;
        *(uint32_t*)(out_hi + base0 + d) = pack_bf16x2(v00, v01);
        *(uint32_t*)(out_lo + base0 + d) = pack_bf16x2(bf16_res(v00), bf16_res(v01));
        *(uint32_t*)(out_hi + base1 + d) = pack_bf16x2(v10, v11);
        *(uint32_t*)(out_lo + base1 + d) = pack_bf16x2(bf16_res(v10), bf16_res(v11));
    }
}

// ============================ launch =======================================
extern "C" void kernel_launch(void* const* d_in, const int* in_sizes, int n_in,
                              void* d_out, int out_size)
{
    const float* hidden = (const float*)d_in[0];
    const float* Wp     = (const float*)d_in[1];
    const float* Wo     = (const float*)d_in[2];
    float* out = (float*)d_out;

    float *qkv = nullptr;
    __nv_bfloat16 *a1hi, *a1lo, *bphi, *bplo, *bohi, *bolo, *athi, *atlo;
    __nv_bfloat16 *qhi, *qlo, *khi, *klo, *vthi, *vtlo;
    cudaGetSymbolAddress((void**)&qkv,  g_qkv);
    cudaGetSymbolAddress((void**)&a1hi, g_a1hi);
    cudaGetSymbolAddress((void**)&a1lo, g_a1lo);
    cudaGetSymbolAddress((void**)&bphi, g_bphi);
    cudaGetSymbolAddress((void**)&bplo, g_bplo);
    cudaGetSymbolAddress((void**)&bohi, g_bohi);
    cudaGetSymbolAddress((void**)&bolo, g_bolo);
    cudaGetSymbolAddress((void**)&athi, g_athi);
    cudaGetSymbolAddress((void**)&atlo, g_atlo);
    cudaGetSymbolAddress((void**)&qhi,  g_qhi);
    cudaGetSymbolAddress((void**)&qlo,  g_qlo);
    cudaGetSymbolAddress((void**)&khi,  g_khi);
    cudaGetSymbolAddress((void**)&klo,  g_klo);
    cudaGetSymbolAddress((void**)&vthi, g_vthi);
    cudaGetSymbolAddress((void**)&vtlo, g_vtlo);

    // Prep: split hidden; transpose+split weights
    split_kernel<<<(M_ROWS * KDIM / 4 + 255) / 256, 256>>>(hidden, a1hi, a1lo, M_ROWS * KDIM / 4);
    transpose_split_kernel<<<dim3(QKV_N / 32, KDIM / 32), dim3(32, 8)>>>(Wp, bphi, bplo, KDIM, QKV_N);
    transpose_split_kernel<<<dim3(HID  / 32, KDIM / 32), dim3(32, 8)>>>(Wo, bohi, bolo, KDIM, HID);

    cudaFuncSetAttribute(hmma_gemm_kernel<0>, cudaFuncAttributeMaxDynamicSharedMemorySize, GEMM_SMEM);
    cudaFuncSetAttribute(hmma_gemm_kernel<1>, cudaFuncAttributeMaxDynamicSharedMemorySize, GEMM_SMEM);
    cudaFuncSetAttribute(attn_kernel, cudaFuncAttributeMaxDynamicSharedMemorySize, ATTN_SMEM);

    // GEMM1: QKV projection -> g_qkv head-major fp32
    hmma_gemm_kernel<1><<<dim3(QKV_N / 128, M_ROWS / 128), 256, GEMM_SMEM>>>(
        a1hi, a1lo, bphi, bplo, qkv);

    // RoPE -> Q/K bf16 hi/lo; V -> V^T bf16 hi/lo
    rope_kernel<<<dim3(SEQ, 2 * BATCH * NHEAD), 64>>>(qkv, qhi, qlo, khi, klo);
    vtrans_kernel<<<dim3(HDIM / 32, SEQ / 32, BATCH * NHEAD), dim3(32, 8)>>>(
        qkv + 2ull * HEAD_ELEMS, vthi, vtlo);

    // Flash attention (HMMA, BM=128) -> bf16 hi/lo
    attn_kernel<<<dim3(SEQ / 128, BATCH * NHEAD), 256, ATTN_SMEM>>>(
        qhi, qlo, khi, klo, vthi, vtlo, athi, atlo);

    // GEMM2: output projection
    hmma_gemm_kernel<0><<<dim3(HID / 128, M_ROWS / 128), 256, GEMM_SMEM>>>(
        athi, atlo, bohi, bolo, out);
}

// round 14
// speedup vs baseline: 1.1901x; 1.0481x over previous
#include <cuda_runtime.h>
#include <cuda_bf16.h>
#include <cstdint>

// ============================ problem constants ============================
#define BATCH 4
#define SEQ   1024
#define HID   4096
#define NHEAD 32
#define HDIM  128
#define M_ROWS (BATCH*SEQ)          // 4096
#define QKV_N  (3*HID)              // 12288
#define KDIM   4096
#define HEAD_ELEMS (BATCH*NHEAD*SEQ*HDIM)  // 16,777,216 per part

// ============================ scratch (device globals) =====================
__device__ __nv_bfloat16 g_a1hi[(size_t)M_ROWS * KDIM];
__device__ __nv_bfloat16 g_a1lo[(size_t)M_ROWS * KDIM];
__device__ __nv_bfloat16 g_bphi[(size_t)QKV_N * KDIM];
__device__ __nv_bfloat16 g_bplo[(size_t)QKV_N * KDIM];
__device__ __nv_bfloat16 g_bohi[(size_t)HID * KDIM];
__device__ __nv_bfloat16 g_bolo[(size_t)HID * KDIM];
__device__ __nv_bfloat16 g_athi[(size_t)M_ROWS * HID];
__device__ __nv_bfloat16 g_atlo[(size_t)M_ROWS * HID];
// attention operands (bf16 hi/lo)
__device__ __nv_bfloat16 g_qhi[(size_t)HEAD_ELEMS];        // [bh][s][d]
__device__ __nv_bfloat16 g_qlo[(size_t)HEAD_ELEMS];
__device__ __nv_bfloat16 g_khi[(size_t)HEAD_ELEMS];
__device__ __nv_bfloat16 g_klo[(size_t)HEAD_ELEMS];
__device__ __nv_bfloat16 g_vthi[(size_t)HEAD_ELEMS];       // [bh][d][s]
__device__ __nv_bfloat16 g_vtlo[(size_t)HEAD_ELEMS];

// ============================ helpers ======================================
__device__ __forceinline__ uint32_t smem_to_u32(const void* p) {
    uint32_t a;
    asm("{ .reg .u64 t; cvta.to.shared.u64 t, %1; cvt.u32.u64 %0, t; }" : "=r"(a) : "l"(p));
    return a;
}

__device__ __forceinline__ void ldmatrix_x4(uint32_t& r0, uint32_t& r1,
                                            uint32_t& r2, uint32_t& r3, uint32_t addr) {
    asm volatile("ldmatrix.sync.aligned.m8n8.x4.shared.b16 {%0,%1,%2,%3}, [%4];"
                 : "=r"(r0), "=r"(r1), "=r"(r2), "=r"(r3) : "r"(addr));
}

__device__ __forceinline__ void mma_bf16(float* d, const uint32_t* a, uint32_t b0, uint32_t b1) {
    asm volatile(
        "mma.sync.aligned.m16n8k16.row.col.f32.bf16.bf16.f32 "
        "{%0,%1,%2,%3}, {%4,%5,%6,%7}, {%8,%9}, {%0,%1,%2,%3};"
        : "+f"(d[0]), "+f"(d[1]), "+f"(d[2]), "+f"(d[3])
        : "r"(a[0]), "r"(a[1]), "r"(a[2]), "r"(a[3]), "r"(b0), "r"(b1));
}

__device__ __forceinline__ uint32_t pack_bf16x2(float x, float y) {
    __nv_bfloat162 t = __floats2bfloat162_rn(x, y);
    return *(uint32_t*)&t;
}
__device__ __forceinline__ float bf16_res(float x) {
    return x - __bfloat162float(__float2bfloat16(x));
}

// ============================ prep kernels =================================
__global__ void split_kernel(const float* __restrict__ x,
                             __nv_bfloat16* __restrict__ hi,
                             __nv_bfloat16* __restrict__ lo, int n4)
{
    int idx = blockIdx.x * blockDim.x + threadIdx.x;
    if (idx >= n4) return;
    float4 v = ((const float4*)x)[idx];
    __nv_bfloat16 h0 = __float2bfloat16(v.x), h1 = __float2bfloat16(v.y);
    __nv_bfloat16 h2 = __float2bfloat16(v.z), h3 = __float2bfloat16(v.w);
    __nv_bfloat16 l0 = __float2bfloat16(v.x - __bfloat162float(h0));
    __nv_bfloat16 l1 = __float2bfloat16(v.y - __bfloat162float(h1));
    __nv_bfloat16 l2 = __float2bfloat16(v.z - __bfloat162float(h2));
    __nv_bfloat16 l3 = __float2bfloat16(v.w - __bfloat162float(h3));
    __nv_bfloat162* hp = (__nv_bfloat162*)hi;
    __nv_bfloat162* lp = (__nv_bfloat162*)lo;
    hp[idx * 2 + 0] = __nv_bfloat162(h0, h1);
    hp[idx * 2 + 1] = __nv_bfloat162(h2, h3);
    lp[idx * 2 + 0] = __nv_bfloat162(l0, l1);
    lp[idx * 2 + 1] = __nv_bfloat162(l2, l3);
}

__global__ void transpose_split_kernel(const float* __restrict__ W,
                                       __nv_bfloat16* __restrict__ hi,
                                       __nv_bfloat16* __restrict__ lo,
                                       int K, int N)
{
    __shared__ float t[32][33];
    int n0 = blockIdx.x * 32, k0 = blockIdx.y * 32;
    int tx = threadIdx.x, ty = threadIdx.y;   // 32 x 8
#pragma unroll
    for (int j = 0; j < 32; j += 8)
        t[ty + j][tx] = W[(size_t)(k0 + ty + j) * N + n0 + tx];
    __syncthreads();
#pragma unroll
    for (int j = 0; j < 32; j += 8) {
        float v = t[tx][ty + j];
        __nv_bfloat16 h = __float2bfloat16(v);
        __nv_bfloat16 l = __float2bfloat16(v - __bfloat162float(h));
        size_t o = (size_t)(n0 + ty + j) * K + k0 + tx;
        hi[o] = h;
        lo[o] = l;
    }
}

// ============================ HMMA GEMM ====================================
// C = (Ahi+Alo)[M,K] @ (Bhi+Blo)^T, fp32 acc, bf16x3 m16n8k16.
// BM=BN=128, BK=64, 256 threads, warps 2(M)x4(N), LDG+STS single buffer.
// EPI=0: C row-major stride HID.
// EPI=1: fused QKV epilogue — stage C tile in smem, then RoPE+split (Q/K) or
//        transpose+split (V) directly to the attention operand arrays.
//        (tile cols = one (part,head): both RoPE halves are CTA-local)
#define BK 64
#define KT_STEPS (KDIM / BK)     // 64
#define ARR 18432                // 128 * 144 bytes
#define GEMM_SMEM (4 * ARR)      // 73728
#define TS_STRIDE 132            // fp32 stage tile row stride

template<int EPI>
__global__ void __launch_bounds__(256, 2)
hmma_gemm_kernel(const __nv_bfloat16* __restrict__ Ahi,
                 const __nv_bfloat16* __restrict__ Alo,
                 const __nv_bfloat16* __restrict__ Bhi,
                 const __nv_bfloat16* __restrict__ Blo,
                 float* __restrict__ C,
                 __nv_bfloat16* __restrict__ oqhi, __nv_bfloat16* __restrict__ oqlo,
                 __nv_bfloat16* __restrict__ okhi, __nv_bfloat16* __restrict__ oklo,
                 __nv_bfloat16* __restrict__ ovthi, __nv_bfloat16* __restrict__ ovtlo)
{
    extern __shared__ __align__(16) char smem[];
    const uint32_t sbase = smem_to_u32(smem);

    const int tid  = threadIdx.x;
    const int lane = tid & 31;
    const int wid  = tid >> 5;
    const int wm   = wid >> 2;
    const int wn   = wid & 3;
    const int bm   = blockIdx.y * 128;
    const int bn   = blockIdx.x * 128;

    const __nv_bfloat16* garr[4] = {Ahi, Alo, Bhi, Blo};

    const uint32_t a_lane = (uint32_t)(lane & 15) * 144 + (uint32_t)(lane >> 4) * 16;
    const uint32_t b_row  = (uint32_t)((lane & 7) | ((lane >> 4) << 3));
    const uint32_t b_lane = b_row * 144 + (uint32_t)((lane >> 3) & 1) * 16;

    float acc[4][4][4];
#pragma unroll
    for (int i = 0; i < 4; i++)
#pragma unroll
        for (int j = 0; j < 4; j++)
#pragma unroll
            for (int r = 0; r < 4; r++) acc[i][j][r] = 0.f;

    for (int kt = 0; kt < KT_STEPS; kt++) {
        const int k0 = kt * BK;
        __syncthreads();
#pragma unroll
        for (int i = 0; i < 16; i++) {
            int arr  = i >> 2;
            int rem  = ((i & 3) << 8) + tid;
            int row  = rem >> 3;
            int part = rem & 7;
            int rbase = (arr < 2) ? bm : bn;
            const uint4* gp = (const uint4*)(garr[arr] + ((size_t)(rbase + row) * KDIM + k0 + part * 8));
            uint4 v = *gp;
            *(uint4*)(smem + arr * ARR + row * 144 + part * 16) = v;
        }
        __syncthreads();

#pragma unroll
        for (int ks = 0; ks < 4; ks++) {
            const uint32_t kb = (uint32_t)ks * 32;

            uint32_t a[4][4], bh[2][4], bl[2][4];
#pragma unroll
            for (int mt = 0; mt < 4; mt++)
                ldmatrix_x4(a[mt][0], a[mt][1], a[mt][2], a[mt][3],
                            sbase + (uint32_t)(wm * 64 + mt * 16) * 144 + kb + a_lane);
#pragma unroll
            for (int n2 = 0; n2 < 2; n2++)
                ldmatrix_x4(bh[n2][0], bh[n2][1], bh[n2][2], bh[n2][3],
                            sbase + 2u * ARR + (uint32_t)(wn * 32 + n2 * 16) * 144 + kb + b_lane);
#pragma unroll
            for (int n2 = 0; n2 < 2; n2++)
                ldmatrix_x4(bl[n2][0], bl[n2][1], bl[n2][2], bl[n2][3],
                            sbase + 3u * ARR + (uint32_t)(wn * 32 + n2 * 16) * 144 + kb + b_lane);

#pragma unroll
            for (int mt = 0; mt < 4; mt++)
#pragma unroll
                for (int nt = 0; nt < 4; nt++) {
                    mma_bf16(acc[mt][nt], a[mt],
                             bh[nt >> 1][(nt & 1) * 2], bh[nt >> 1][(nt & 1) * 2 + 1]);
                    mma_bf16(acc[mt][nt], a[mt],
                             bl[nt >> 1][(nt & 1) * 2], bl[nt >> 1][(nt & 1) * 2 + 1]);
                }

#pragma unroll
            for (int mt = 0; mt < 4; mt++)
                ldmatrix_x4(a[mt][0], a[mt][1], a[mt][2], a[mt][3],
                            sbase + ARR + (uint32_t)(wm * 64 + mt * 16) * 144 + kb + a_lane);
#pragma unroll
            for (int mt = 0; mt < 4; mt++)
#pragma unroll
                for (int nt = 0; nt < 4; nt++)
                    mma_bf16(acc[mt][nt], a[mt],
                             bh[nt >> 1][(nt & 1) * 2], bh[nt >> 1][(nt & 1) * 2 + 1]);
        }
    }

    if (EPI == 0) {
#pragma unroll
        for (int mt = 0; mt < 4; mt++) {
#pragma unroll
            for (int half = 0; half < 2; half++) {
                int row = bm + wm * 64 + mt * 16 + (lane >> 2) + half * 8;
#pragma unroll
                for (int nt = 0; nt < 4; nt++) {
                    int col = bn + wn * 32 + nt * 8 + (lane & 3) * 2;
                    C[(size_t)row * HID + col]     = acc[mt][nt][half * 2 + 0];
                    C[(size_t)row * HID + col + 1] = acc[mt][nt][half * 2 + 1];
                }
            }
        }
    } else {
        // ---- fused QKV epilogue: stage tile in smem (reuses operand buffer) ----
        __syncthreads();   // all warps done reading operands
        float* TS = (float*)smem;
#pragma unroll
        for (int mt = 0; mt < 4; mt++)
#pragma unroll
            for (int half = 0; half < 2; half++) {
                int r = wm * 64 + mt * 16 + (lane >> 2) + half * 8;
#pragma unroll
                for (int nt = 0; nt < 4; nt++) {
                    int c = wn * 32 + nt * 8 + (lane & 3) * 2;
                    TS[r * TS_STRIDE + c]     = acc[mt][nt][half * 2 + 0];
                    TS[r * TS_STRIDE + c + 1] = acc[mt][nt][half * 2 + 1];
                }
            }
        __syncthreads();

        const int part = bn >> 12;
        const int h    = (bn >> 7) & 31;
        const int b    = bm >> 10;          // 128-row tile never crosses batch
        const int s0   = bm & 1023;
        const int bh   = b * NHEAD + h;

        if (part < 2) {
            __nv_bfloat16* hi = part ? okhi : oqhi;
            __nv_bfloat16* lo = part ? oklo : oqlo;
            const int d = tid & 63;          // loop-invariant per thread
            const float e = (float)(2 * d) * (1.0f / 128.0f);
            const float inv_freq = 1.0f / powf(10000.0f, e);
            for (int i = tid; i < 8192; i += 256) {
                int r = i >> 6;
                int s = s0 + r;
                float fr = (float)s * inv_freq;
                float cc = cosf(fr), sn = sinf(fr);
                float x1 = TS[r * TS_STRIDE + d];
                float x2 = TS[r * TS_STRIDE + d + 64];
                float y1 = x1 * cc - x2 * sn;
                float y2 = x2 * cc + x1 * sn;
                size_t ob = ((size_t)bh * SEQ + s) * HDIM;
                __nv_bfloat16 h1 = __float2bfloat16(y1);
                __nv_bfloat16 h2 = __float2bfloat16(y2);
                hi[ob + d]      = h1;
                hi[ob + d + 64] = h2;
                lo[ob + d]      = __float2bfloat16(y1 - __bfloat162float(h1));
                lo[ob + d + 64] = __float2bfloat16(y2 - __bfloat162float(h2));
            }
        } else {
            size_t vb = (size_t)bh * HDIM * SEQ;
            for (int i = tid; i < 16384; i += 256) {
                int d  = i >> 7;
                int sl = i & 127;
                float v = TS[sl * TS_STRIDE + d];
                __nv_bfloat16 hh = __float2bfloat16(v);
                size_t o = vb + (size_t)d * SEQ + s0 + sl;
                ovthi[o] = hh;
                ovtlo[o] = __float2bfloat16(v - __bfloat162float(hh));
            }
        }
    }
}

// ============================ HMMA flash attention (R13, unchanged) ========
#define AT_QROW 272
#define AT_VROW 144
#define AT_QHI 0
#define AT_QLO 34816
#define AT_KHI 69632
#define AT_KLO 87040
#define AT_VHI 104448
#define AT_VLO 122880
#define ATTN_SMEM 141312

__global__ void __launch_bounds__(256, 1)
attn_kernel(const __nv_bfloat16* __restrict__ qhi, const __nv_bfloat16* __restrict__ qlo,
            const __nv_bfloat16* __restrict__ khi, const __nv_bfloat16* __restrict__ klo,
            const __nv_bfloat16* __restrict__ vthi, const __nv_bfloat16* __restrict__ vtlo,
            __nv_bfloat16* __restrict__ out_hi, __nv_bfloat16* __restrict__ out_lo)
{
    extern __shared__ __align__(16) char sm[];
    const uint32_t sb = smem_to_u32(sm);

    const int tid  = threadIdx.x;
    const int lane = tid & 31;
    const int w    = tid >> 5;
    const int bh   = blockIdx.y;
    const int b    = bh >> 5;
    const int h    = bh & 31;
    const int q0   = blockIdx.x * 128;
    const size_t hoff  = (size_t)bh * SEQ * HDIM;
    const size_t vbase = (size_t)bh * HDIM * SEQ;

    const uint32_t a_lane  = (uint32_t)(lane & 15) * AT_QROW + (uint32_t)(lane >> 4) * 16;
    const uint32_t b_row   = (uint32_t)((lane & 7) | ((lane >> 4) << 3));
    const uint32_t bk_lane = b_row * AT_QROW + (uint32_t)((lane >> 3) & 1) * 16;
    const uint32_t bv_lane = b_row * AT_VROW + (uint32_t)((lane >> 3) & 1) * 16;

    for (int i = tid; i < 4096; i += 256) {
        int arr = i >> 11, rem = i & 2047;
        int r = rem >> 4, c = rem & 15;
        const __nv_bfloat16* src = (arr ? qlo : qhi) + hoff + (size_t)(q0 + r) * HDIM + c * 8;
        uint4 v = *(const uint4*)src;
        *(uint4*)(sm + (arr ? AT_QLO : AT_QHI) + r * AT_QROW + c * 16) = v;
    }

    const int g = lane >> 2;
    const int qq0 = q0 + w * 16 + g;
    const int qq1 = qq0 + 8;
    const int wrow_lo = q0 + w * 16;
    const int wrow_hi = wrow_lo + 15;
    const float scale = 0.08838834764831845f;

    float oa[16][4];
#pragma unroll
    for (int i = 0; i < 16; i++)
#pragma unroll
        for (int r = 0; r < 4; r++) oa[i][r] = 0.f;
    float m0 = -1e30f, m1 = -1e30f, l0 = 0.f, l1 = 0.f;

    const int ktmax = 2 * blockIdx.x + 1;
    for (int kt = 0; kt <= ktmax; kt++) {
        const int k0 = kt * 64;
        __syncthreads();
        for (int i = tid; i < 4096; i += 256) {
            if (i < 2048) {
                int arr = i >> 10, rem = i & 1023;
                int r = rem >> 4, c = rem & 15;
                const __nv_bfloat16* src = (arr ? klo : khi) + hoff + (size_t)(k0 + r) * HDIM + c * 8;
                uint4 v = *(const uint4*)src;
                *(uint4*)(sm + (arr ? AT_KLO : AT_KHI) + r * AT_QROW + c * 16) = v;
            } else {
                int i2 = i - 2048;
                int arr = i2 >> 10, rem = i2 & 1023;
                int r = rem >> 3, c = rem & 7;
                const __nv_bfloat16* src = (arr ? vtlo : vthi) + vbase + (size_t)r * SEQ + k0 + c * 8;
                uint4 v = *(const uint4*)src;
                *(uint4*)(sm + (arr ? AT_VLO : AT_VHI) + r * AT_VROW + c * 16) = v;
            }
        }
        __syncthreads();

        if (k0 > wrow_hi) continue;

        float sc[8][4];
#pragma unroll
        for (int j = 0; j < 8; j++)
#pragma unroll
            for (int r = 0; r < 4; r++) sc[j][r] = 0.f;

#pragma unroll
        for (int ks = 0; ks < 8; ks++) {
            const uint32_t kb = (uint32_t)ks * 32;
            uint32_t ah[4], al[4], kh[4][4], kl[4][4];
            ldmatrix_x4(ah[0], ah[1], ah[2], ah[3],
                        sb + AT_QHI + (uint32_t)(w * 16) * AT_QROW + kb + a_lane);
            ldmatrix_x4(al[0], al[1], al[2], al[3],
                        sb + AT_QLO + (uint32_t)(w * 16) * AT_QROW + kb + a_lane);
#pragma unroll
            for (int j2 = 0; j2 < 4; j2++) {
                ldmatrix_x4(kh[j2][0], kh[j2][1], kh[j2][2], kh[j2][3],
                            sb + AT_KHI + (uint32_t)(j2 * 16) * AT_QROW + kb + bk_lane);
                ldmatrix_x4(kl[j2][0], kl[j2][1], kl[j2][2], kl[j2][3],
                            sb + AT_KLO + (uint32_t)(j2 * 16) * AT_QROW + kb + bk_lane);
            }
#pragma unroll
            for (int j = 0; j < 8; j++) {
                uint32_t b0h = kh[j >> 1][(j & 1) * 2], b1h = kh[j >> 1][(j & 1) * 2 + 1];
                uint32_t b0l = kl[j >> 1][(j & 1) * 2], b1l = kl[j >> 1][(j & 1) * 2 + 1];
                mma_bf16(sc[j], ah, b0h, b1h);
                mma_bf16(sc[j], ah, b0l, b1l);
                mma_bf16(sc[j], al, b0h, b1h);
            }
        }

        if (k0 + 63 > wrow_lo) {
#pragma unroll
            for (int j = 0; j < 8; j++) {
                int c0 = k0 + j * 8 + (lane & 3) * 2;
                sc[j][0] = sc[j][0] * scale + ((c0     <= qq0) ? 0.f : -1e9f);
                sc[j][1] = sc[j][1] * scale + ((c0 + 1 <= qq0) ? 0.f : -1e9f);
                sc[j][2] = sc[j][2] * scale + ((c0     <= qq1) ? 0.f : -1e9f);
                sc[j][3] = sc[j][3] * scale + ((c0 + 1 <= qq1) ? 0.f : -1e9f);
            }
        } else {
#pragma unroll
            for (int j = 0; j < 8; j++)
#pragma unroll
                for (int r = 0; r < 4; r++) sc[j][r] *= scale;
        }

        float mx0 = -1e30f, mx1 = -1e30f;
#pragma unroll
        for (int j = 0; j < 8; j++) {
            mx0 = fmaxf(mx0, fmaxf(sc[j][0], sc[j][1]));
            mx1 = fmaxf(mx1, fmaxf(sc[j][2], sc[j][3]));
        }
        mx0 = fmaxf(mx0, __shfl_xor_sync(0xffffffffu, mx0, 1));
        mx0 = fmaxf(mx0, __shfl_xor_sync(0xffffffffu, mx0, 2));
        mx1 = fmaxf(mx1, __shfl_xor_sync(0xffffffffu, mx1, 1));
        mx1 = fmaxf(mx1, __shfl_xor_sync(0xffffffffu, mx1, 2));
        float mn0 = fmaxf(m0, mx0), mn1 = fmaxf(m1, mx1);
        float al0 = __expf(m0 - mn0), al1 = __expf(m1 - mn1);

        float s0 = 0.f, s1 = 0.f;
#pragma unroll
        for (int j = 0; j < 8; j++) {
            sc[j][0] = __expf(sc[j][0] - mn0); s0 += sc[j][0];
            sc[j][1] = __expf(sc[j][1] - mn0); s0 += sc[j][1];
            sc[j][2] = __expf(sc[j][2] - mn1); s1 += sc[j][2];
            sc[j][3] = __expf(sc[j][3] - mn1); s1 += sc[j][3];
        }
        s0 += __shfl_xor_sync(0xffffffffu, s0, 1);
        s0 += __shfl_xor_sync(0xffffffffu, s0, 2);
        s1 += __shfl_xor_sync(0xffffffffu, s1, 1);
        s1 += __shfl_xor_sync(0xffffffffu, s1, 2);
        l0 = l0 * al0 + s0; m0 = mn0;
        l1 = l1 * al1 + s1; m1 = mn1;

#pragma unroll
        for (int i = 0; i < 16; i++) {
            oa[i][0] *= al0; oa[i][1] *= al0;
            oa[i][2] *= al1; oa[i][3] *= al1;
        }

        uint32_t pfh[4][4], pfl[4][4];
#pragma unroll
        for (int t = 0; t < 4; t++) {
            int j = 2 * t;
            pfh[t][0] = pack_bf16x2(sc[j][0],     sc[j][1]);
            pfh[t][1] = pack_bf16x2(sc[j][2],     sc[j][3]);
            pfh[t][2] = pack_bf16x2(sc[j + 1][0], sc[j + 1][1]);
            pfh[t][3] = pack_bf16x2(sc[j + 1][2], sc[j + 1][3]);
            pfl[t][0] = pack_bf16x2(bf16_res(sc[j][0]),     bf16_res(sc[j][1]));
            pfl[t][1] = pack_bf16x2(bf16_res(sc[j][2]),     bf16_res(sc[j][3]));
            pfl[t][2] = pack_bf16x2(bf16_res(sc[j + 1][0]), bf16_res(sc[j + 1][1]));
            pfl[t][3] = pack_bf16x2(bf16_res(sc[j + 1][2]), bf16_res(sc[j + 1][3]));
        }

#pragma unroll
        for (int t = 0; t < 4; t++) {
            const uint32_t kb = (uint32_t)t * 32;
#pragma unroll
            for (int n2 = 0; n2 < 8; n2++) {
                uint32_t vh[4], vl[4];
                ldmatrix_x4(vh[0], vh[1], vh[2], vh[3],
                            sb + AT_VHI + (uint32_t)(n2 * 16) * AT_VROW + kb + bv_lane);
                ldmatrix_x4(vl[0], vl[1], vl[2], vl[3],
                            sb + AT_VLO + (uint32_t)(n2 * 16) * AT_VROW + kb + bv_lane);
#pragma unroll
                for (int q = 0; q < 2; q++) {
                    int nt = n2 * 2 + q;
                    mma_bf16(oa[nt], pfh[t], vh[q * 2], vh[q * 2 + 1]);
                    mma_bf16(oa[nt], pfh[t], vl[q * 2], vl[q * 2 + 1]);
                    mma_bf16(oa[nt], pfl[t], vh[q * 2], vh[q * 2 + 1]);
                }
            }
        }
    }

    float il0 = 1.f / l0, il1 = 1.f / l1;
    size_t base0 = ((size_t)(b * SEQ + qq0)) * HID + (size_t)h * HDIM;
    size_t base1 = ((size_t)(b * SEQ + qq1)) * HID + (size_t)h * HDIM;
#pragma unroll
    for (int nt = 0; nt < 16; nt++) {
        int d = nt * 8 + (lane & 3) * 2;
        float v00 = oa[nt][0] * il0, v01 = oa[nt][1] * il0;
        float v10 = oa[nt][2] * il1, v11 = oa[nt][3] * il1;
        *(uint32_t*)(out_hi + base0 + d) = pack_bf16x2(v00, v01);
        *(uint32_t*)(out_lo + base0 + d) = pack_bf16x2(bf16_res(v00), bf16_res(v01));
        *(uint32_t*)(out_hi + base1 + d) = pack_bf16x2(v10, v11);
        *(uint32_t*)(out_lo + base1 + d) = pack_bf16x2(bf16_res(v10), bf16_res(v11));
    }
}

// ============================ launch =======================================
extern "C" void kernel_launch(void* const* d_in, const int* in_sizes, int n_in,
                              void* d_out, int out_size)
{
    const float* hidden = (const float*)d_in[0];
    const float* Wp     = (const float*)d_in[1];
    const float* Wo     = (const float*)d_in[2];
    float* out = (float*)d_out;

    __nv_bfloat16 *a1hi, *a1lo, *bphi, *bplo, *bohi, *bolo, *athi, *atlo;
    __nv_bfloat16 *qhi, *qlo, *khi, *klo, *vthi, *vtlo;
    cudaGetSymbolAddress((void**)&a1hi, g_a1hi);
    cudaGetSymbolAddress((void**)&a1lo, g_a1lo);
    cudaGetSymbolAddress((void**)&bphi, g_bphi);
    cudaGetSymbolAddress((void**)&bplo, g_bplo);
    cudaGetSymbolAddress((void**)&bohi, g_bohi);
    cudaGetSymbolAddress((void**)&bolo, g_bolo);
    cudaGetSymbolAddress((void**)&athi, g_athi);
    cudaGetSymbolAddress((void**)&atlo, g_atlo);
    cudaGetSymbolAddress((void**)&qhi,  g_qhi);
    cudaGetSymbolAddress((void**)&qlo,  g_qlo);
    cudaGetSymbolAddress((void**)&khi,  g_khi);
    cudaGetSymbolAddress((void**)&klo,  g_klo);
    cudaGetSymbolAddress((void**)&vthi, g_vthi);
    cudaGetSymbolAddress((void**)&vtlo, g_vtlo);

    // Prep: split hidden; transpose+split weights
    split_kernel<<<(M_ROWS * KDIM / 4 + 255) / 256, 256>>>(hidden, a1hi, a1lo, M_ROWS * KDIM / 4);
    transpose_split_kernel<<<dim3(QKV_N / 32, KDIM / 32), dim3(32, 8)>>>(Wp, bphi, bplo, KDIM, QKV_N);
    transpose_split_kernel<<<dim3(HID  / 32, KDIM / 32), dim3(32, 8)>>>(Wo, bohi, bolo, KDIM, HID);

    cudaFuncSetAttribute(hmma_gemm_kernel<0>, cudaFuncAttributeMaxDynamicSharedMemorySize, GEMM_SMEM);
    cudaFuncSetAttribute(hmma_gemm_kernel<1>, cudaFuncAttributeMaxDynamicSharedMemorySize, GEMM_SMEM);
    cudaFuncSetAttribute(attn_kernel, cudaFuncAttributeMaxDynamicSharedMemorySize, ATTN_SMEM);

    // GEMM1: QKV projection with fused RoPE / V-transpose / bf16-split epilogue
    hmma_gemm_kernel<1><<<dim3(QKV_N / 128, M_ROWS / 128), 256, GEMM_SMEM>>>(
        a1hi, a1lo, bphi, bplo, nullptr,
        qhi, qlo, khi, klo, vthi, vtlo);

    // Flash attention (HMMA, BM=128) -> bf16 hi/lo
    attn_kernel<<<dim3(SEQ / 128, BATCH * NHEAD), 256, ATTN_SMEM>>>(
        qhi, qlo, khi, klo, vthi, vtlo, athi, atlo);

    // GEMM2: output projection
    hmma_gemm_kernel<0><<<dim3(HID / 128, M_ROWS / 128), 256, GEMM_SMEM>>>(
        athi, atlo, bohi, bolo, out,
        nullptr, nullptr, nullptr, nullptr, nullptr, nullptr);
}

// round 15
// speedup vs baseline: 2.8294x; 2.3776x over previous
#include <cuda_runtime.h>
#include <cuda_fp16.h>
#include <cstdint>

// ============================ problem constants ============================
#define BATCH 4
#define SEQ   1024
#define HID   4096
#define NHEAD 32
#define HDIM  128
#define M_ROWS (BATCH*SEQ)          // 4096
#define QKV_N  (3*HID)              // 12288
#define KDIM   4096
#define HEAD_ELEMS (BATCH*NHEAD*SEQ*HDIM)  // 16,777,216 per part

// ============================ scratch (device globals) =====================
__device__ __half g_a1[(size_t)M_ROWS * KDIM];      // hidden fp16 [m][k]
__device__ __half g_bp[(size_t)QKV_N * KDIM];       // W_pack^T fp16 [n][k]
__device__ __half g_bo[(size_t)HID * KDIM];         // W_o^T fp16 [n][k]
__device__ __half g_at[(size_t)M_ROWS * HID];       // attn out fp16 [m][k]
__device__ __half g_q [(size_t)HEAD_ELEMS];         // [bh][s][d]
__device__ __half g_k [(size_t)HEAD_ELEMS];
__device__ __half g_vt[(size_t)HEAD_ELEMS];         // [bh][d][s]

// ============================ helpers ======================================
__device__ __forceinline__ uint32_t smem_to_u32(const void* p) {
    uint32_t a;
    asm("{ .reg .u64 t; cvta.to.shared.u64 t, %1; cvt.u32.u64 %0, t; }" : "=r"(a) : "l"(p));
    return a;
}

__device__ __forceinline__ void ldmatrix_x4(uint32_t& r0, uint32_t& r1,
                                            uint32_t& r2, uint32_t& r3, uint32_t addr) {
    asm volatile("ldmatrix.sync.aligned.m8n8.x4.shared.b16 {%0,%1,%2,%3}, [%4];"
                 : "=r"(r0), "=r"(r1), "=r"(r2), "=r"(r3) : "r"(addr));
}

__device__ __forceinline__ void mma_fp16(float* d, const uint32_t* a, uint32_t b0, uint32_t b1) {
    asm volatile(
        "mma.sync.aligned.m16n8k16.row.col.f32.f16.f16.f32 "
        "{%0,%1,%2,%3}, {%4,%5,%6,%7}, {%8,%9}, {%0,%1,%2,%3};"
        : "+f"(d[0]), "+f"(d[1]), "+f"(d[2]), "+f"(d[3])
        : "r"(a[0]), "r"(a[1]), "r"(a[2]), "r"(a[3]), "r"(b0), "r"(b1));
}

__device__ __forceinline__ uint32_t pack_half2(float x, float y) {
    __half2 t = __floats2half2_rn(x, y);
    return *(uint32_t*)&t;
}

// ============================ prep kernels =================================
__global__ void convert_kernel(const float* __restrict__ x,
                               __half* __restrict__ y, int n4)
{
    int idx = blockIdx.x * blockDim.x + threadIdx.x;
    if (idx >= n4) return;
    float4 v = ((const float4*)x)[idx];
    __half2* yp = (__half2*)y;
    yp[idx * 2 + 0] = __floats2half2_rn(v.x, v.y);
    yp[idx * 2 + 1] = __floats2half2_rn(v.z, v.w);
}

__global__ void transpose_convert_kernel(const float* __restrict__ W,
                                         __half* __restrict__ out, int K, int N)
{
    __shared__ float t[32][33];
    int n0 = blockIdx.x * 32, k0 = blockIdx.y * 32;
    int tx = threadIdx.x, ty = threadIdx.y;   // 32 x 8
#pragma unroll
    for (int j = 0; j < 32; j += 8)
        t[ty + j][tx] = W[(size_t)(k0 + ty + j) * N + n0 + tx];
    __syncthreads();
#pragma unroll
    for (int j = 0; j < 32; j += 8)
        out[(size_t)(n0 + ty + j) * K + k0 + tx] = __float2half(t[tx][ty + j]);
}

// ============================ HMMA GEMM (fp16 x1) ==========================
// C[M,N] = A[M,K] @ B^T (B stored [N][K] K-major), fp16 inputs, fp32 acc.
// BM=BN=128, BK=64, 256 threads, warps 2(M)x4(N), LDG+STS single buffer.
// EPI=0: C row-major stride HID.
// EPI=1: fused QKV epilogue (stage fp32 tile in smem; RoPE for Q/K parts,
//        transpose for V part; fp16 outputs).
#define BK 64
#define KT_STEPS (KDIM / BK)     // 64
#define ARR 18432                // 128 * 144 bytes
#define TS_STRIDE 132
#define GEMM_SMEM0 (2 * ARR)     // 36864
#define GEMM_SMEM1 67584         // 128*132*4 staging (covers operands too)

template<int EPI>
__global__ void __launch_bounds__(256, 2)
hmma_gemm_kernel(const __half* __restrict__ A,
                 const __half* __restrict__ B,
                 float* __restrict__ C,
                 __half* __restrict__ oq, __half* __restrict__ ok,
                 __half* __restrict__ ovt)
{
    extern __shared__ __align__(16) char smem[];
    const uint32_t sbase = smem_to_u32(smem);

    const int tid  = threadIdx.x;
    const int lane = tid & 31;
    const int wid  = tid >> 5;
    const int wm   = wid >> 2;
    const int wn   = wid & 3;
    const int bm   = blockIdx.y * 128;
    const int bn   = blockIdx.x * 128;

    const uint32_t a_lane = (uint32_t)(lane & 15) * 144 + (uint32_t)(lane >> 4) * 16;
    const uint32_t b_row  = (uint32_t)((lane & 7) | ((lane >> 4) << 3));
    const uint32_t b_lane = b_row * 144 + (uint32_t)((lane >> 3) & 1) * 16;

    float acc[4][4][4];
#pragma unroll
    for (int i = 0; i < 4; i++)
#pragma unroll
        for (int j = 0; j < 4; j++)
#pragma unroll
            for (int r = 0; r < 4; r++) acc[i][j][r] = 0.f;

    for (int kt = 0; kt < KT_STEPS; kt++) {
        const int k0 = kt * BK;
        __syncthreads();
        // ---- load A,B tiles: 2 arrays x [128 rows x 64 fp16], 8 chunks/thr --
#pragma unroll
        for (int i = 0; i < 8; i++) {
            int arr  = i >> 2;
            int rem  = ((i & 3) << 8) + tid;
            int row  = rem >> 3;
            int part = rem & 7;
            const __half* g = arr ? B : A;
            int rbase = arr ? bn : bm;
            const uint4* gp = (const uint4*)(g + ((size_t)(rbase + row) * KDIM + k0 + part * 8));
            uint4 v = *gp;
            *(uint4*)(smem + arr * ARR + row * 144 + part * 16) = v;
        }
        __syncthreads();

#pragma unroll
        for (int ks = 0; ks < 4; ks++) {
            const uint32_t kb = (uint32_t)ks * 32;
            uint32_t a[4][4], bf[2][4];
#pragma unroll
            for (int mt = 0; mt < 4; mt++)
                ldmatrix_x4(a[mt][0], a[mt][1], a[mt][2], a[mt][3],
                            sbase + (uint32_t)(wm * 64 + mt * 16) * 144 + kb + a_lane);
#pragma unroll
            for (int n2 = 0; n2 < 2; n2++)
                ldmatrix_x4(bf[n2][0], bf[n2][1], bf[n2][2], bf[n2][3],
                            sbase + (uint32_t)ARR + (uint32_t)(wn * 32 + n2 * 16) * 144 + kb + b_lane);
#pragma unroll
            for (int mt = 0; mt < 4; mt++)
#pragma unroll
                for (int nt = 0; nt < 4; nt++)
                    mma_fp16(acc[mt][nt], a[mt],
                             bf[nt >> 1][(nt & 1) * 2], bf[nt >> 1][(nt & 1) * 2 + 1]);
        }
    }

    if (EPI == 0) {
#pragma unroll
        for (int mt = 0; mt < 4; mt++) {
#pragma unroll
            for (int half = 0; half < 2; half++) {
                int row = bm + wm * 64 + mt * 16 + (lane >> 2) + half * 8;
#pragma unroll
                for (int nt = 0; nt < 4; nt++) {
                    int col = bn + wn * 32 + nt * 8 + (lane & 3) * 2;
                    C[(size_t)row * HID + col]     = acc[mt][nt][half * 2 + 0];
                    C[(size_t)row * HID + col + 1] = acc[mt][nt][half * 2 + 1];
                }
            }
        }
    } else {
        // ---- fused QKV epilogue ----
        __syncthreads();
        float* TS = (float*)smem;
#pragma unroll
        for (int mt = 0; mt < 4; mt++)
#pragma unroll
            for (int half = 0; half < 2; half++) {
                int r = wm * 64 + mt * 16 + (lane >> 2) + half * 8;
#pragma unroll
                for (int nt = 0; nt < 4; nt++) {
                    int c = wn * 32 + nt * 8 + (lane & 3) * 2;
                    TS[r * TS_STRIDE + c]     = acc[mt][nt][half * 2 + 0];
                    TS[r * TS_STRIDE + c + 1] = acc[mt][nt][half * 2 + 1];
                }
            }
        __syncthreads();

        const int part = bn >> 12;
        const int h    = (bn >> 7) & 31;
        const int b    = bm >> 10;
        const int s0   = bm & 1023;
        const int bh   = b * NHEAD + h;

        if (part < 2) {
            __half* dst = part ? ok : oq;
            const int d = tid & 63;
            const float e = (float)(2 * d) * (1.0f / 128.0f);
            const float inv_freq = 1.0f / powf(10000.0f, e);
            for (int i = tid; i < 8192; i += 256) {
                int r = i >> 6;
                int s = s0 + r;
                float fr = (float)s * inv_freq;
                float cc = cosf(fr), sn = sinf(fr);
                float x1 = TS[r * TS_STRIDE + d];
                float x2 = TS[r * TS_STRIDE + d + 64];
                size_t ob = ((size_t)bh * SEQ + s) * HDIM;
                dst[ob + d]      = __float2half(x1 * cc - x2 * sn);
                dst[ob + d + 64] = __float2half(x2 * cc + x1 * sn);
            }
        } else {
            size_t vb = (size_t)bh * HDIM * SEQ;
            for (int i = tid; i < 16384; i += 256) {
                int d  = i >> 7;
                int sl = i & 127;
                ovt[vb + (size_t)d * SEQ + s0 + sl] = __float2half(TS[sl * TS_STRIDE + d]);
            }
        }
    }
}

// ============================ HMMA flash attention (fp16 x1) ===============
// 256 threads (8 warps), BM=128, BN=64, D=128. Warp w owns rows [w*16,w*16+16).
#define AT_QROW 272
#define AT_VROW 144
#define AT_Q 0
#define AT_K 34816
#define AT_V 52224
#define ATTN_SMEM 70656

__global__ void __launch_bounds__(256, 2)
attn_kernel(const __half* __restrict__ q, const __half* __restrict__ k,
            const __half* __restrict__ vt, __half* __restrict__ outp)
{
    extern __shared__ __align__(16) char sm[];
    const uint32_t sb = smem_to_u32(sm);

    const int tid  = threadIdx.x;
    const int lane = tid & 31;
    const int w    = tid >> 5;
    const int bh   = blockIdx.y;
    const int b    = bh >> 5;
    const int h    = bh & 31;
    const int q0   = blockIdx.x * 128;
    const size_t hoff  = (size_t)bh * SEQ * HDIM;
    const size_t vbase = (size_t)bh * HDIM * SEQ;

    const uint32_t a_lane  = (uint32_t)(lane & 15) * AT_QROW + (uint32_t)(lane >> 4) * 16;
    const uint32_t b_row   = (uint32_t)((lane & 7) | ((lane >> 4) << 3));
    const uint32_t bk_lane = b_row * AT_QROW + (uint32_t)((lane >> 3) & 1) * 16;
    const uint32_t bv_lane = b_row * AT_VROW + (uint32_t)((lane >> 3) & 1) * 16;

    // ---- load Q (128 rows x 128 fp16, 272B rows) ----
    for (int i = tid; i < 2048; i += 256) {
        int r = i >> 4, c = i & 15;
        uint4 v = *(const uint4*)(q + hoff + (size_t)(q0 + r) * HDIM + c * 8);
        *(uint4*)(sm + AT_Q + r * AT_QROW + c * 16) = v;
    }

    const int g = lane >> 2;
    const int qq0 = q0 + w * 16 + g;
    const int qq1 = qq0 + 8;
    const int wrow_lo = q0 + w * 16;
    const int wrow_hi = wrow_lo + 15;
    const float scale = 0.08838834764831845f;

    float oa[16][4];
#pragma unroll
    for (int i = 0; i < 16; i++)
#pragma unroll
        for (int r = 0; r < 4; r++) oa[i][r] = 0.f;
    float m0 = -1e30f, m1 = -1e30f, l0 = 0.f, l1 = 0.f;

    const int ktmax = 2 * blockIdx.x + 1;
    for (int kt = 0; kt <= ktmax; kt++) {
        const int k0 = kt * 64;
        __syncthreads();
        // ---- load K (64x128) + Vt (128x64) ----
        for (int i = tid; i < 2048; i += 256) {
            if (i < 1024) {
                int r = i >> 4, c = i & 15;
                uint4 v = *(const uint4*)(k + hoff + (size_t)(k0 + r) * HDIM + c * 8);
                *(uint4*)(sm + AT_K + r * AT_QROW + c * 16) = v;
            } else {
                int i2 = i - 1024;
                int r = i2 >> 3, c = i2 & 7;
                uint4 v = *(const uint4*)(vt + vbase + (size_t)r * SEQ + k0 + c * 8);
                *(uint4*)(sm + AT_V + r * AT_VROW + c * 16) = v;
            }
        }
        __syncthreads();

        if (k0 > wrow_hi) continue;

        // ---- S = QK^T ----
        float sc[8][4];
#pragma unroll
        for (int j = 0; j < 8; j++)
#pragma unroll
            for (int r = 0; r < 4; r++) sc[j][r] = 0.f;

#pragma unroll
        for (int ks = 0; ks < 8; ks++) {
            const uint32_t kb = (uint32_t)ks * 32;
            uint32_t qa[4], kf[4][4];
            ldmatrix_x4(qa[0], qa[1], qa[2], qa[3],
                        sb + AT_Q + (uint32_t)(w * 16) * AT_QROW + kb + a_lane);
#pragma unroll
            for (int j2 = 0; j2 < 4; j2++)
                ldmatrix_x4(kf[j2][0], kf[j2][1], kf[j2][2], kf[j2][3],
                            sb + AT_K + (uint32_t)(j2 * 16) * AT_QROW + kb + bk_lane);
#pragma unroll
            for (int j = 0; j < 8; j++)
                mma_fp16(sc[j], qa, kf[j >> 1][(j & 1) * 2], kf[j >> 1][(j & 1) * 2 + 1]);
        }

        // ---- scale (+ causal mask on diagonal-overlap tiles) ----
        if (k0 + 63 > wrow_lo) {
#pragma unroll
            for (int j = 0; j < 8; j++) {
                int c0 = k0 + j * 8 + (lane & 3) * 2;
                sc[j][0] = sc[j][0] * scale + ((c0     <= qq0) ? 0.f : -1e9f);
                sc[j][1] = sc[j][1] * scale + ((c0 + 1 <= qq0) ? 0.f : -1e9f);
                sc[j][2] = sc[j][2] * scale + ((c0     <= qq1) ? 0.f : -1e9f);
                sc[j][3] = sc[j][3] * scale + ((c0 + 1 <= qq1) ? 0.f : -1e9f);
            }
        } else {
#pragma unroll
            for (int j = 0; j < 8; j++)
#pragma unroll
                for (int r = 0; r < 4; r++) sc[j][r] *= scale;
        }

        // ---- online softmax ----
        float mx0 = -1e30f, mx1 = -1e30f;
#pragma unroll
        for (int j = 0; j < 8; j++) {
            mx0 = fmaxf(mx0, fmaxf(sc[j][0], sc[j][1]));
            mx1 = fmaxf(mx1, fmaxf(sc[j][2], sc[j][3]));
        }
        mx0 = fmaxf(mx0, __shfl_xor_sync(0xffffffffu, mx0, 1));
        mx0 = fmaxf(mx0, __shfl_xor_sync(0xffffffffu, mx0, 2));
        mx1 = fmaxf(mx1, __shfl_xor_sync(0xffffffffu, mx1, 1));
        mx1 = fmaxf(mx1, __shfl_xor_sync(0xffffffffu, mx1, 2));
        float mn0 = fmaxf(m0, mx0), mn1 = fmaxf(m1, mx1);
        float al0 = __expf(m0 - mn0), al1 = __expf(m1 - mn1);

        float s0 = 0.f, s1 = 0.f;
#pragma unroll
        for (int j = 0; j < 8; j++) {
            sc[j][0] = __expf(sc[j][0] - mn0); s0 += sc[j][0];
            sc[j][1] = __expf(sc[j][1] - mn0); s0 += sc[j][1];
            sc[j][2] = __expf(sc[j][2] - mn1); s1 += sc[j][2];
            sc[j][3] = __expf(sc[j][3] - mn1); s1 += sc[j][3];
        }
        s0 += __shfl_xor_sync(0xffffffffu, s0, 1);
        s0 += __shfl_xor_sync(0xffffffffu, s0, 2);
        s1 += __shfl_xor_sync(0xffffffffu, s1, 1);
        s1 += __shfl_xor_sync(0xffffffffu, s1, 2);
        l0 = l0 * al0 + s0; m0 = mn0;
        l1 = l1 * al1 + s1; m1 = mn1;

#pragma unroll
        for (int i = 0; i < 16; i++) {
            oa[i][0] *= al0; oa[i][1] *= al0;
            oa[i][2] *= al1; oa[i][3] *= al1;
        }

        // ---- P -> A fragments ----
        uint32_t pf[4][4];
#pragma unroll
        for (int t = 0; t < 4; t++) {
            int j = 2 * t;
            pf[t][0] = pack_half2(sc[j][0],     sc[j][1]);
            pf[t][1] = pack_half2(sc[j][2],     sc[j][3]);
            pf[t][2] = pack_half2(sc[j + 1][0], sc[j + 1][1]);
            pf[t][3] = pack_half2(sc[j + 1][2], sc[j + 1][3]);
        }

        // ---- O += P @ V ----
#pragma unroll
        for (int t = 0; t < 4; t++) {
            const uint32_t kb = (uint32_t)t * 32;
#pragma unroll
            for (int n2 = 0; n2 < 8; n2++) {
                uint32_t vf[4];
                ldmatrix_x4(vf[0], vf[1], vf[2], vf[3],
                            sb + AT_V + (uint32_t)(n2 * 16) * AT_VROW + kb + bv_lane);
#pragma unroll
                for (int qh = 0; qh < 2; qh++)
                    mma_fp16(oa[n2 * 2 + qh], pf[t], vf[qh * 2], vf[qh * 2 + 1]);
            }
        }
    }

    // ---- epilogue: normalize, fp16, store [b][s][h*128+d] ----
    float il0 = 1.f / l0, il1 = 1.f / l1;
    size_t base0 = ((size_t)(b * SEQ + qq0)) * HID + (size_t)h * HDIM;
    size_t base1 = ((size_t)(b * SEQ + qq1)) * HID + (size_t)h * HDIM;
#pragma unroll
    for (int nt = 0; nt < 16; nt++) {
        int d = nt * 8 + (lane & 3) * 2;
        *(uint32_t*)(outp + base0 + d) = pack_half2(oa[nt][0] * il0, oa[nt][1] * il0);
        *(uint32_t*)(outp + base1 + d) = pack_half2(oa[nt][2] * il1, oa[nt][3] * il1);
    }
}

// ============================ launch =======================================
extern "C" void kernel_launch(void* const* d_in, const int* in_sizes, int n_in,
                              void* d_out, int out_size)
{
    const float* hidden = (const float*)d_in[0];
    const float* Wp     = (const float*)d_in[1];
    const float* Wo     = (const float*)d_in[2];
    float* out = (float*)d_out;

    __half *a1, *bp, *bo, *at, *qh, *kh, *vth;
    cudaGetSymbolAddress((void**)&a1,  g_a1);
    cudaGetSymbolAddress((void**)&bp,  g_bp);
    cudaGetSymbolAddress((void**)&bo,  g_bo);
    cudaGetSymbolAddress((void**)&at,  g_at);
    cudaGetSymbolAddress((void**)&qh,  g_q);
    cudaGetSymbolAddress((void**)&kh,  g_k);
    cudaGetSymbolAddress((void**)&vth, g_vt);

    // Prep: convert hidden; transpose+convert weights
    convert_kernel<<<(M_ROWS * KDIM / 4 + 255) / 256, 256>>>(hidden, a1, M_ROWS * KDIM / 4);
    transpose_convert_kernel<<<dim3(QKV_N / 32, KDIM / 32), dim3(32, 8)>>>(Wp, bp, KDIM, QKV_N);
    transpose_convert_kernel<<<dim3(HID  / 32, KDIM / 32), dim3(32, 8)>>>(Wo, bo, KDIM, HID);

    cudaFuncSetAttribute(hmma_gemm_kernel<0>, cudaFuncAttributeMaxDynamicSharedMemorySize, GEMM_SMEM0);
    cudaFuncSetAttribute(hmma_gemm_kernel<1>, cudaFuncAttributeMaxDynamicSharedMemorySize, GEMM_SMEM1);
    cudaFuncSetAttribute(attn_kernel, cudaFuncAttributeMaxDynamicSharedMemorySize, ATTN_SMEM);

    // GEMM1: QKV projection with fused RoPE / V-transpose epilogue
    hmma_gemm_kernel<1><<<dim3(QKV_N / 128, M_ROWS / 128), 256, GEMM_SMEM1>>>(
        a1, bp, nullptr, qh, kh, vth);

    // Flash attention (HMMA fp16, BM=128)
    attn_kernel<<<dim3(SEQ / 128, BATCH * NHEAD), 256, ATTN_SMEM>>>(
        qh, kh, vth, at);

    // GEMM2: output projection
    hmma_gemm_kernel<0><<<dim3(HID / 128, M_ROWS / 128), 256, GEMM_SMEM0>>>(
        at, bo, out, nullptr, nullptr, nullptr);
}

// round 16
// speedup vs baseline: 2.9495x; 1.0424x over previous
#include <cuda_runtime.h>
#include <cuda_fp16.h>
#include <cstdint>

// ============================ problem constants ============================
#define BATCH 4
#define SEQ   1024
#define HID   4096
#define NHEAD 32
#define HDIM  128
#define M_ROWS (BATCH*SEQ)          // 4096
#define QKV_N  (3*HID)              // 12288
#define KDIM   4096
#define HEAD_ELEMS (BATCH*NHEAD*SEQ*HDIM)  // 16,777,216 per part

// ============================ scratch (device globals) =====================
__device__ __half g_a1[(size_t)M_ROWS * KDIM];      // hidden fp16 [m][k]
__device__ __half g_bp[(size_t)QKV_N * KDIM];       // W_pack^T fp16 [n][k]
__device__ __half g_bo[(size_t)HID * KDIM];         // W_o^T fp16 [n][k]
__device__ __half g_at[(size_t)M_ROWS * HID];       // attn out fp16 [m][k]
__device__ __half g_q [(size_t)HEAD_ELEMS];         // [bh][s][d]
__device__ __half g_k [(size_t)HEAD_ELEMS];
__device__ __half g_vt[(size_t)HEAD_ELEMS];         // [bh][d][s]

// ============================ helpers ======================================
__device__ __forceinline__ uint32_t smem_to_u32(const void* p) {
    uint32_t a;
    asm("{ .reg .u64 t; cvta.to.shared.u64 t, %1; cvt.u32.u64 %0, t; }" : "=r"(a) : "l"(p));
    return a;
}

__device__ __forceinline__ void ldmatrix_x4(uint32_t& r0, uint32_t& r1,
                                            uint32_t& r2, uint32_t& r3, uint32_t addr) {
    asm volatile("ldmatrix.sync.aligned.m8n8.x4.shared.b16 {%0,%1,%2,%3}, [%4];"
                 : "=r"(r0), "=r"(r1), "=r"(r2), "=r"(r3) : "r"(addr));
}

__device__ __forceinline__ void mma_fp16(float* d, const uint32_t* a, uint32_t b0, uint32_t b1) {
    asm volatile(
        "mma.sync.aligned.m16n8k16.row.col.f32.f16.f16.f32 "
        "{%0,%1,%2,%3}, {%4,%5,%6,%7}, {%8,%9}, {%0,%1,%2,%3};"
        : "+f"(d[0]), "+f"(d[1]), "+f"(d[2]), "+f"(d[3])
        : "r"(a[0]), "r"(a[1]), "r"(a[2]), "r"(a[3]), "r"(b0), "r"(b1));
}

__device__ __forceinline__ uint32_t pack_half2(float x, float y) {
    __half2 t = __floats2half2_rn(x, y);
    return *(uint32_t*)&t;
}

// ============================ prep kernels =================================
__global__ void convert_kernel(const float* __restrict__ x,
                               __half* __restrict__ y, int n4)
{
    int idx = blockIdx.x * blockDim.x + threadIdx.x;
    if (idx >= n4) return;
    float4 v = ((const float4*)x)[idx];
    __half2* yp = (__half2*)y;
    yp[idx * 2 + 0] = __floats2half2_rn(v.x, v.y);
    yp[idx * 2 + 1] = __floats2half2_rn(v.z, v.w);
}

__global__ void transpose_convert_kernel(const float* __restrict__ W,
                                         __half* __restrict__ out, int K, int N)
{
    __shared__ float t[32][33];
    int n0 = blockIdx.x * 32, k0 = blockIdx.y * 32;
    int tx = threadIdx.x, ty = threadIdx.y;   // 32 x 8
#pragma unroll
    for (int j = 0; j < 32; j += 8)
        t[ty + j][tx] = W[(size_t)(k0 + ty + j) * N + n0 + tx];
    __syncthreads();
#pragma unroll
    for (int j = 0; j < 32; j += 8)
        out[(size_t)(n0 + ty + j) * K + k0 + tx] = __float2half(t[tx][ty + j]);
}

// ============================ HMMA GEMM (fp16 x1, fat warp tiles) ==========
// C[M,N] = A[M,K] @ B^T, fp16 in, fp32 acc. BM=BN=128, BK=64, 128 threads,
// 4 warps in 2x2 grid, per-warp 64x64 (4x8 m16n8 tiles) -> 8 LDSM per 32 MMA.
// EPI=0: C row-major stride HID. EPI=1: fused RoPE/V-transpose epilogue.
#define BK 64
#define KT_STEPS (KDIM / BK)     // 64
#define ARR 18432                // 128 * 144 bytes
#define TS_STRIDE 132
#define GEMM_SMEM0 (2 * ARR)     // 36864
#define GEMM_SMEM1 67584         // 128*132*4 staging (covers operands too)

template<int EPI>
__global__ void __launch_bounds__(128, 2)
hmma_gemm_kernel(const __half* __restrict__ A,
                 const __half* __restrict__ B,
                 float* __restrict__ C,
                 __half* __restrict__ oq, __half* __restrict__ ok,
                 __half* __restrict__ ovt)
{
    extern __shared__ __align__(16) char smem[];
    const uint32_t sbase = smem_to_u32(smem);

    const int tid  = threadIdx.x;
    const int lane = tid & 31;
    const int wid  = tid >> 5;        // 0..3
    const int wm   = wid >> 1;        // 0..1
    const int wn   = wid & 1;         // 0..1
    const int bm   = blockIdx.y * 128;
    const int bn   = blockIdx.x * 128;

    const uint32_t a_lane = (uint32_t)(lane & 15) * 144 + (uint32_t)(lane >> 4) * 16;
    const uint32_t b_row  = (uint32_t)((lane & 7) | ((lane >> 4) << 3));
    const uint32_t b_lane = b_row * 144 + (uint32_t)((lane >> 3) & 1) * 16;

    float acc[4][8][4];
#pragma unroll
    for (int i = 0; i < 4; i++)
#pragma unroll
        for (int j = 0; j < 8; j++)
#pragma unroll
            for (int r = 0; r < 4; r++) acc[i][j][r] = 0.f;

    for (int kt = 0; kt < KT_STEPS; kt++) {
        const int k0 = kt * BK;
        __syncthreads();
        // ---- load A,B tiles: 2 arrays x [128 rows x 64 fp16], 16 chunks/thr
#pragma unroll
        for (int i = 0; i < 16; i++) {
            int arr  = i >> 3;
            int rem  = ((i & 7) << 7) + tid;   // 0..1023
            int row  = rem >> 3;
            int part = rem & 7;
            const __half* g = arr ? B : A;
            int rbase = arr ? bn : bm;
            const uint4* gp = (const uint4*)(g + ((size_t)(rbase + row) * KDIM + k0 + part * 8));
            uint4 v = *gp;
            *(uint4*)(smem + arr * ARR + row * 144 + part * 16) = v;
        }
        __syncthreads();

#pragma unroll
        for (int ks = 0; ks < 4; ks++) {
            const uint32_t kb = (uint32_t)ks * 32;
            uint32_t a[4][4], bf[4][4];
#pragma unroll
            for (int mt = 0; mt < 4; mt++)
                ldmatrix_x4(a[mt][0], a[mt][1], a[mt][2], a[mt][3],
                            sbase + (uint32_t)(wm * 64 + mt * 16) * 144 + kb + a_lane);
#pragma unroll
            for (int n2 = 0; n2 < 4; n2++)
                ldmatrix_x4(bf[n2][0], bf[n2][1], bf[n2][2], bf[n2][3],
                            sbase + (uint32_t)ARR + (uint32_t)(wn * 64 + n2 * 16) * 144 + kb + b_lane);
#pragma unroll
            for (int mt = 0; mt < 4; mt++)
#pragma unroll
                for (int nt = 0; nt < 8; nt++)
                    mma_fp16(acc[mt][nt], a[mt],
                             bf[nt >> 1][(nt & 1) * 2], bf[nt >> 1][(nt & 1) * 2 + 1]);
        }
    }

    if (EPI == 0) {
#pragma unroll
        for (int mt = 0; mt < 4; mt++) {
#pragma unroll
            for (int half = 0; half < 2; half++) {
                int row = bm + wm * 64 + mt * 16 + (lane >> 2) + half * 8;
#pragma unroll
                for (int nt = 0; nt < 8; nt++) {
                    int col = bn + wn * 64 + nt * 8 + (lane & 3) * 2;
                    C[(size_t)row * HID + col]     = acc[mt][nt][half * 2 + 0];
                    C[(size_t)row * HID + col + 1] = acc[mt][nt][half * 2 + 1];
                }
            }
        }
    } else {
        // ---- fused QKV epilogue: stage fp32 tile, then RoPE / V-transpose ----
        __syncthreads();
        float* TS = (float*)smem;
#pragma unroll
        for (int mt = 0; mt < 4; mt++)
#pragma unroll
            for (int half = 0; half < 2; half++) {
                int r = wm * 64 + mt * 16 + (lane >> 2) + half * 8;
#pragma unroll
                for (int nt = 0; nt < 8; nt++) {
                    int c = wn * 64 + nt * 8 + (lane & 3) * 2;
                    TS[r * TS_STRIDE + c]     = acc[mt][nt][half * 2 + 0];
                    TS[r * TS_STRIDE + c + 1] = acc[mt][nt][half * 2 + 1];
                }
            }
        __syncthreads();

        const int part = bn >> 12;
        const int h    = (bn >> 7) & 31;
        const int b    = bm >> 10;
        const int s0   = bm & 1023;
        const int bh   = b * NHEAD + h;

        if (part < 2) {
            __half* dst = part ? ok : oq;
            const int d = tid & 63;
            const float e = (float)(2 * d) * (1.0f / 128.0f);
            const float inv_freq = 1.0f / powf(10000.0f, e);
            for (int i = tid; i < 8192; i += 128) {
                int r = i >> 6;
                int s = s0 + r;
                float fr = (float)s * inv_freq;
                float cc = cosf(fr), sn = sinf(fr);
                float x1 = TS[r * TS_STRIDE + d];
                float x2 = TS[r * TS_STRIDE + d + 64];
                size_t ob = ((size_t)bh * SEQ + s) * HDIM;
                dst[ob + d]      = __float2half(x1 * cc - x2 * sn);
                dst[ob + d + 64] = __float2half(x2 * cc + x1 * sn);
            }
        } else {
            size_t vb = (size_t)bh * HDIM * SEQ;
            for (int i = tid; i < 16384; i += 128) {
                int d  = i >> 7;
                int sl = i & 127;
                ovt[vb + (size_t)d * SEQ + s0 + sl] = __float2half(TS[sl * TS_STRIDE + d]);
            }
        }
    }
}

// ============================ HMMA flash attention (fp16, R15 unchanged) ===
#define AT_QROW 272
#define AT_VROW 144
#define AT_Q 0
#define AT_K 34816
#define AT_V 52224
#define ATTN_SMEM 70656

__global__ void __launch_bounds__(256, 2)
attn_kernel(const __half* __restrict__ q, const __half* __restrict__ k,
            const __half* __restrict__ vt, __half* __restrict__ outp)
{
    extern __shared__ __align__(16) char sm[];
    const uint32_t sb = smem_to_u32(sm);

    const int tid  = threadIdx.x;
    const int lane = tid & 31;
    const int w    = tid >> 5;
    const int bh   = blockIdx.y;
    const int b    = bh >> 5;
    const int h    = bh & 31;
    const int q0   = blockIdx.x * 128;
    const size_t hoff  = (size_t)bh * SEQ * HDIM;
    const size_t vbase = (size_t)bh * HDIM * SEQ;

    const uint32_t a_lane  = (uint32_t)(lane & 15) * AT_QROW + (uint32_t)(lane >> 4) * 16;
    const uint32_t b_row   = (uint32_t)((lane & 7) | ((lane >> 4) << 3));
    const uint32_t bk_lane = b_row * AT_QROW + (uint32_t)((lane >> 3) & 1) * 16;
    const uint32_t bv_lane = b_row * AT_VROW + (uint32_t)((lane >> 3) & 1) * 16;

    for (int i = tid; i < 2048; i += 256) {
        int r = i >> 4, c = i & 15;
        uint4 v = *(const uint4*)(q + hoff + (size_t)(q0 + r) * HDIM + c * 8);
        *(uint4*)(sm + AT_Q + r * AT_QROW + c * 16) = v;
    }

    const int g = lane >> 2;
    const int qq0 = q0 + w * 16 + g;
    const int qq1 = qq0 + 8;
    const int wrow_lo = q0 + w * 16;
    const int wrow_hi = wrow_lo + 15;
    const float scale = 0.08838834764831845f;

    float oa[16][4];
#pragma unroll
    for (int i = 0; i < 16; i++)
#pragma unroll
        for (int r = 0; r < 4; r++) oa[i][r] = 0.f;
    float m0 = -1e30f, m1 = -1e30f, l0 = 0.f, l1 = 0.f;

    const int ktmax = 2 * blockIdx.x + 1;
    for (int kt = 0; kt <= ktmax; kt++) {
        const int k0 = kt * 64;
        __syncthreads();
        for (int i = tid; i < 2048; i += 256) {
            if (i < 1024) {
                int r = i >> 4, c = i & 15;
                uint4 v = *(const uint4*)(k + hoff + (size_t)(k0 + r) * HDIM + c * 8);
                *(uint4*)(sm + AT_K + r * AT_QROW + c * 16) = v;
            } else {
                int i2 = i - 1024;
                int r = i2 >> 3, c = i2 & 7;
                uint4 v = *(const uint4*)(vt + vbase + (size_t)r * SEQ + k0 + c * 8);
                *(uint4*)(sm + AT_V + r * AT_VROW + c * 16) = v;
            }
        }
        __syncthreads();

        if (k0 > wrow_hi) continue;

        float sc[8][4];
#pragma unroll
        for (int j = 0; j < 8; j++)
#pragma unroll
            for (int r = 0; r < 4; r++) sc[j][r] = 0.f;

#pragma unroll
        for (int ks = 0; ks < 8; ks++) {
            const uint32_t kb = (uint32_t)ks * 32;
            uint32_t qa[4], kf[4][4];
            ldmatrix_x4(qa[0], qa[1], qa[2], qa[3],
                        sb + AT_Q + (uint32_t)(w * 16) * AT_QROW + kb + a_lane);
#pragma unroll
            for (int j2 = 0; j2 < 4; j2++)
                ldmatrix_x4(kf[j2][0], kf[j2][1], kf[j2][2], kf[j2][3],
                            sb + AT_K + (uint32_t)(j2 * 16) * AT_QROW + kb + bk_lane);
#pragma unroll
            for (int j = 0; j < 8; j++)
                mma_fp16(sc[j], qa, kf[j >> 1][(j & 1) * 2], kf[j >> 1][(j & 1) * 2 + 1]);
        }

        if (k0 + 63 > wrow_lo) {
#pragma unroll
            for (int j = 0; j < 8; j++) {
                int c0 = k0 + j * 8 + (lane & 3) * 2;
                sc[j][0] = sc[j][0] * scale + ((c0     <= qq0) ? 0.f : -1e9f);
                sc[j][1] = sc[j][1] * scale + ((c0 + 1 <= qq0) ? 0.f : -1e9f);
                sc[j][2] = sc[j][2] * scale + ((c0     <= qq1) ? 0.f : -1e9f);
                sc[j][3] = sc[j][3] * scale + ((c0 + 1 <= qq1) ? 0.f : -1e9f);
            }
        } else {
#pragma unroll
            for (int j = 0; j < 8; j++)
#pragma unroll
                for (int r = 0; r < 4; r++) sc[j][r] *= scale;
        }

        float mx0 = -1e30f, mx1 = -1e30f;
#pragma unroll
        for (int j = 0; j < 8; j++) {
            mx0 = fmaxf(mx0, fmaxf(sc[j][0], sc[j][1]));
            mx1 = fmaxf(mx1, fmaxf(sc[j][2], sc[j][3]));
        }
        mx0 = fmaxf(mx0, __shfl_xor_sync(0xffffffffu, mx0, 1));
        mx0 = fmaxf(mx0, __shfl_xor_sync(0xffffffffu, mx0, 2));
        mx1 = fmaxf(mx1, __shfl_xor_sync(0xffffffffu, mx1, 1));
        mx1 = fmaxf(mx1, __shfl_xor_sync(0xffffffffu, mx1, 2));
        float mn0 = fmaxf(m0, mx0), mn1 = fmaxf(m1, mx1);
        float al0 = __expf(m0 - mn0), al1 = __expf(m1 - mn1);

        float s0 = 0.f, s1 = 0.f;
#pragma unroll
        for (int j = 0; j < 8; j++) {
            sc[j][0] = __expf(sc[j][0] - mn0); s0 += sc[j][0];
            sc[j][1] = __expf(sc[j][1] - mn0); s0 += sc[j][1];
            sc[j][2] = __expf(sc[j][2] - mn1); s1 += sc[j][2];
            sc[j][3] = __expf(sc[j][3] - mn1); s1 += sc[j][3];
        }
        s0 += __shfl_xor_sync(0xffffffffu, s0, 1);
        s0 += __shfl_xor_sync(0xffffffffu, s0, 2);
        s1 += __shfl_xor_sync(0xffffffffu, s1, 1);
        s1 += __shfl_xor_sync(0xffffffffu, s1, 2);
        l0 = l0 * al0 + s0; m0 = mn0;
        l1 = l1 * al1 + s1; m1 = mn1;

#pragma unroll
        for (int i = 0; i < 16; i++) {
            oa[i][0] *= al0; oa[i][1] *= al0;
            oa[i][2] *= al1; oa[i][3] *= al1;
        }

        uint32_t pf[4][4];
#pragma unroll
        for (int t = 0; t < 4; t++) {
            int j = 2 * t;
            pf[t][0] = pack_half2(sc[j][0],     sc[j][1]);
            pf[t][1] = pack_half2(sc[j][2],     sc[j][3]);
            pf[t][2] = pack_half2(sc[j + 1][0], sc[j + 1][1]);
            pf[t][3] = pack_half2(sc[j + 1][2], sc[j + 1][3]);
        }

#pragma unroll
        for (int t = 0; t < 4; t++) {
            const uint32_t kb = (uint32_t)t * 32;
#pragma unroll
            for (int n2 = 0; n2 < 8; n2++) {
                uint32_t vf[4];
                ldmatrix_x4(vf[0], vf[1], vf[2], vf[3],
                            sb + AT_V + (uint32_t)(n2 * 16) * AT_VROW + kb + bv_lane);
#pragma unroll
                for (int qh = 0; qh < 2; qh++)
                    mma_fp16(oa[n2 * 2 + qh], pf[t], vf[qh * 2], vf[qh * 2 + 1]);
            }
        }
    }

    float il0 = 1.f / l0, il1 = 1.f / l1;
    size_t base0 = ((size_t)(b * SEQ + qq0)) * HID + (size_t)h * HDIM;
    size_t base1 = ((size_t)(b * SEQ + qq1)) * HID + (size_t)h * HDIM;
#pragma unroll
    for (int nt = 0; nt < 16; nt++) {
        int d = nt * 8 + (lane & 3) * 2;
        *(uint32_t*)(outp + base0 + d) = pack_half2(oa[nt][0] * il0, oa[nt][1] * il0);
        *(uint32_t*)(outp + base1 + d) = pack_half2(oa[nt][2] * il1, oa[nt][3] * il1);
    }
}

// ============================ launch =======================================
extern "C" void kernel_launch(void* const* d_in, const int* in_sizes, int n_in,
                              void* d_out, int out_size)
{
    const float* hidden = (const float*)d_in[0];
    const float* Wp     = (const float*)d_in[1];
    const float* Wo     = (const float*)d_in[2];
    float* out = (float*)d_out;

    __half *a1, *bp, *bo, *at, *qh, *kh, *vth;
    cudaGetSymbolAddress((void**)&a1,  g_a1);
    cudaGetSymbolAddress((void**)&bp,  g_bp);
    cudaGetSymbolAddress((void**)&bo,  g_bo);
    cudaGetSymbolAddress((void**)&at,  g_at);
    cudaGetSymbolAddress((void**)&qh,  g_q);
    cudaGetSymbolAddress((void**)&kh,  g_k);
    cudaGetSymbolAddress((void**)&vth, g_vt);

    // Prep: convert hidden; transpose+convert weights
    convert_kernel<<<(M_ROWS * KDIM / 4 + 255) / 256, 256>>>(hidden, a1, M_ROWS * KDIM / 4);
    transpose_convert_kernel<<<dim3(QKV_N / 32, KDIM / 32), dim3(32, 8)>>>(Wp, bp, KDIM, QKV_N);
    transpose_convert_kernel<<<dim3(HID  / 32, KDIM / 32), dim3(32, 8)>>>(Wo, bo, KDIM, HID);

    cudaFuncSetAttribute(hmma_gemm_kernel<0>, cudaFuncAttributeMaxDynamicSharedMemorySize, GEMM_SMEM0);
    cudaFuncSetAttribute(hmma_gemm_kernel<1>, cudaFuncAttributeMaxDynamicSharedMemorySize, GEMM_SMEM1);
    cudaFuncSetAttribute(attn_kernel, cudaFuncAttributeMaxDynamicSharedMemorySize, ATTN_SMEM);

    // GEMM1: QKV projection with fused RoPE / V-transpose epilogue
    hmma_gemm_kernel<1><<<dim3(QKV_N / 128, M_ROWS / 128), 128, GEMM_SMEM1>>>(
        a1, bp, nullptr, qh, kh, vth);

    // Flash attention (HMMA fp16, BM=128)
    attn_kernel<<<dim3(SEQ / 128, BATCH * NHEAD), 256, ATTN_SMEM>>>(
        qh, kh, vth, at);

    // GEMM2: output projection
    hmma_gemm_kernel<0><<<dim3(HID / 128, M_ROWS / 128), 128, GEMM_SMEM0>>>(
        at, bo, out, nullptr, nullptr, nullptr);
}

// round 17
// speedup vs baseline: 3.1122x; 1.0552x over previous
#include <cuda_runtime.h>
#include <cuda_fp16.h>
#include <cstdint>

// ============================ problem constants ============================
#define BATCH 4
#define SEQ   1024
#define HID   4096
#define NHEAD 32
#define HDIM  128
#define M_ROWS (BATCH*SEQ)          // 4096
#define QKV_N  (3*HID)              // 12288
#define KDIM   4096
#define HEAD_ELEMS (BATCH*NHEAD*SEQ*HDIM)  // 16,777,216 per part

// ============================ scratch (device globals) =====================
__device__ __half g_a1[(size_t)M_ROWS * KDIM];      // hidden fp16 [m][k]
__device__ __half g_bp[(size_t)QKV_N * KDIM];       // W_pack^T fp16 [n][k]
__device__ __half g_bo[(size_t)HID * KDIM];         // W_o^T fp16 [n][k]
__device__ __half g_at[(size_t)M_ROWS * HID];       // attn out fp16 [m][k]
__device__ __half g_q [(size_t)HEAD_ELEMS];         // [bh][s][d]
__device__ __half g_k [(size_t)HEAD_ELEMS];
__device__ __half g_vt[(size_t)HEAD_ELEMS];         // [bh][d][s]

// ============================ helpers ======================================
__device__ __forceinline__ uint32_t smem_to_u32(const void* p) {
    uint32_t a;
    asm("{ .reg .u64 t; cvta.to.shared.u64 t, %1; cvt.u32.u64 %0, t; }" : "=r"(a) : "l"(p));
    return a;
}

__device__ __forceinline__ void ldmatrix_x4(uint32_t& r0, uint32_t& r1,
                                            uint32_t& r2, uint32_t& r3, uint32_t addr) {
    asm volatile("ldmatrix.sync.aligned.m8n8.x4.shared.b16 {%0,%1,%2,%3}, [%4];"
                 : "=r"(r0), "=r"(r1), "=r"(r2), "=r"(r3) : "r"(addr));
}

__device__ __forceinline__ void mma_fp16(float* d, const uint32_t* a, uint32_t b0, uint32_t b1) {
    asm volatile(
        "mma.sync.aligned.m16n8k16.row.col.f32.f16.f16.f32 "
        "{%0,%1,%2,%3}, {%4,%5,%6,%7}, {%8,%9}, {%0,%1,%2,%3};"
        : "+f"(d[0]), "+f"(d[1]), "+f"(d[2]), "+f"(d[3])
        : "r"(a[0]), "r"(a[1]), "r"(a[2]), "r"(a[3]), "r"(b0), "r"(b1));
}

__device__ __forceinline__ uint32_t pack_half2(float x, float y) {
    __half2 t = __floats2half2_rn(x, y);
    return *(uint32_t*)&t;
}

// ============================ prep kernels =================================
__global__ void convert_kernel(const float* __restrict__ x,
                               __half* __restrict__ y, int n4)
{
    int idx = blockIdx.x * blockDim.x + threadIdx.x;
    if (idx >= n4) return;
    float4 v = ((const float4*)x)[idx];
    __half2* yp = (__half2*)y;
    yp[idx * 2 + 0] = __floats2half2_rn(v.x, v.y);
    yp[idx * 2 + 1] = __floats2half2_rn(v.z, v.w);
}

__global__ void transpose_convert_kernel(const float* __restrict__ W,
                                         __half* __restrict__ out, int K, int N)
{
    __shared__ float t[32][33];
    int n0 = blockIdx.x * 32, k0 = blockIdx.y * 32;
    int tx = threadIdx.x, ty = threadIdx.y;   // 32 x 8
#pragma unroll
    for (int j = 0; j < 32; j += 8)
        t[ty + j][tx] = W[(size_t)(k0 + ty + j) * N + n0 + tx];
    __syncthreads();
#pragma unroll
    for (int j = 0; j < 32; j += 8)
        out[(size_t)(n0 + ty + j) * K + k0 + tx] = __float2half(t[tx][ty + j]);
}

// ============================ HMMA GEMM (fp16, 3-stage cp.async) ===========
// C[M,N] = A[M,K] @ B^T, fp16 in, fp32 acc. BM=BN=128, BK=64, 128 threads,
// 4 warps 2x2, per-warp 64x64. 3-stage cp.async.ca ring, 2 CTAs/SM,
// one __syncthreads per K-tile; loads kt+1 and kt+2 in flight during compute.
// EPI=0: C row-major stride HID. EPI=1: fused RoPE/V-transpose epilogue.
#define BK 64
#define KT_STEPS (KDIM / BK)     // 64
#define ARR 18432                // 128 * 144 bytes
#define STAGE (2 * ARR)          // 36864
#define GEMM_SMEM (3 * STAGE)    // 110592 (covers 67584 EPI=1 staging)
#define TS_STRIDE 132

template<int EPI>
__global__ void __launch_bounds__(128, 2)
hmma_gemm_kernel(const __half* __restrict__ A,
                 const __half* __restrict__ B,
                 float* __restrict__ C,
                 __half* __restrict__ oq, __half* __restrict__ ok,
                 __half* __restrict__ ovt)
{
    extern __shared__ __align__(16) char smem[];
    const uint32_t sbase = smem_to_u32(smem);

    const int tid  = threadIdx.x;
    const int lane = tid & 31;
    const int wid  = tid >> 5;        // 0..3
    const int wm   = wid >> 1;        // 0..1
    const int wn   = wid & 1;         // 0..1
    const int bm   = blockIdx.y * 128;
    const int bn   = blockIdx.x * 128;

    const uint32_t a_lane = (uint32_t)(lane & 15) * 144 + (uint32_t)(lane >> 4) * 16;
    const uint32_t b_row  = (uint32_t)((lane & 7) | ((lane >> 4) << 3));
    const uint32_t b_lane = b_row * 144 + (uint32_t)((lane >> 3) & 1) * 16;

    // loader decode (loop-invariant): 2048 chunks/stage, 16/thread
    const int lrow = tid >> 3;        // 0..15 base row
    const int lc   = tid & 7;         // 16B chunk within 128B row

    auto load_stage = [&](int slot, int k0) {
        uint32_t sb2 = sbase + (uint32_t)slot * STAGE;
#pragma unroll
        for (int i = 0; i < 16; i++) {
            int arr = i >> 3;                    // 0=A, 1=B
            int row = lrow + (i & 7) * 16;       // 0..127
            const __half* g = arr ? B : A;
            int rbase = arr ? bn : bm;
            const void* gp = g + ((size_t)(rbase + row) * KDIM + k0 + lc * 8);
            uint32_t so = sb2 + (uint32_t)(arr * ARR + row * 144 + lc * 16);
            asm volatile("cp.async.ca.shared.global [%0], [%1], 16;" :: "r"(so), "l"(gp));
        }
        asm volatile("cp.async.commit_group;" ::: "memory");
    };

    float acc[4][8][4];
#pragma unroll
    for (int i = 0; i < 4; i++)
#pragma unroll
        for (int j = 0; j < 8; j++)
#pragma unroll
            for (int r = 0; r < 4; r++) acc[i][j][r] = 0.f;

    load_stage(0, 0);
    load_stage(1, BK);

    int cur = 0;
    for (int kt = 0; kt < KT_STEPS; kt++) {
        if (kt + 1 < KT_STEPS) {
            asm volatile("cp.async.wait_group 1;" ::: "memory");
        } else {
            asm volatile("cp.async.wait_group 0;" ::: "memory");
        }
        __syncthreads();   // tile kt visible to all; all warps done with slot (cur+2)%3

        int nslot = cur + 2; if (nslot >= 3) nslot -= 3;
        if (kt + 2 < KT_STEPS) load_stage(nslot, (kt + 2) * BK);

        const uint32_t buf = sbase + (uint32_t)cur * STAGE;
#pragma unroll
        for (int ks = 0; ks < 4; ks++) {
            const uint32_t kb = (uint32_t)ks * 32;
            uint32_t a[4][4], bf[4][4];
#pragma unroll
            for (int mt = 0; mt < 4; mt++)
                ldmatrix_x4(a[mt][0], a[mt][1], a[mt][2], a[mt][3],
                            buf + (uint32_t)(wm * 64 + mt * 16) * 144 + kb + a_lane);
#pragma unroll
            for (int n2 = 0; n2 < 4; n2++)
                ldmatrix_x4(bf[n2][0], bf[n2][1], bf[n2][2], bf[n2][3],
                            buf + (uint32_t)ARR + (uint32_t)(wn * 64 + n2 * 16) * 144 + kb + b_lane);
#pragma unroll
            for (int mt = 0; mt < 4; mt++)
#pragma unroll
                for (int nt = 0; nt < 8; nt++)
                    mma_fp16(acc[mt][nt], a[mt],
                             bf[nt >> 1][(nt & 1) * 2], bf[nt >> 1][(nt & 1) * 2 + 1]);
        }
        cur = (cur + 1 == 3) ? 0 : cur + 1;
    }

    if (EPI == 0) {
#pragma unroll
        for (int mt = 0; mt < 4; mt++) {
#pragma unroll
            for (int half = 0; half < 2; half++) {
                int row = bm + wm * 64 + mt * 16 + (lane >> 2) + half * 8;
#pragma unroll
                for (int nt = 0; nt < 8; nt++) {
                    int col = bn + wn * 64 + nt * 8 + (lane & 3) * 2;
                    C[(size_t)row * HID + col]     = acc[mt][nt][half * 2 + 0];
                    C[(size_t)row * HID + col + 1] = acc[mt][nt][half * 2 + 1];
                }
            }
        }
    } else {
        // ---- fused QKV epilogue: stage fp32 tile, then RoPE / V-transpose ----
        __syncthreads();
        float* TS = (float*)smem;
#pragma unroll
        for (int mt = 0; mt < 4; mt++)
#pragma unroll
            for (int half = 0; half < 2; half++) {
                int r = wm * 64 + mt * 16 + (lane >> 2) + half * 8;
#pragma unroll
                for (int nt = 0; nt < 8; nt++) {
                    int c = wn * 64 + nt * 8 + (lane & 3) * 2;
                    TS[r * TS_STRIDE + c]     = acc[mt][nt][half * 2 + 0];
                    TS[r * TS_STRIDE + c + 1] = acc[mt][nt][half * 2 + 1];
                }
            }
        __syncthreads();

        const int part = bn >> 12;
        const int h    = (bn >> 7) & 31;
        const int b    = bm >> 10;
        const int s0   = bm & 1023;
        const int bh   = b * NHEAD + h;

        if (part < 2) {
            __half* dst = part ? ok : oq;
            const int d = tid & 63;
            const float e = (float)(2 * d) * (1.0f / 128.0f);
            const float inv_freq = 1.0f / powf(10000.0f, e);
            for (int i = tid; i < 8192; i += 128) {
                int r = i >> 6;
                int s = s0 + r;
                float fr = (float)s * inv_freq;
                float cc = cosf(fr), sn = sinf(fr);
                float x1 = TS[r * TS_STRIDE + d];
                float x2 = TS[r * TS_STRIDE + d + 64];
                size_t ob = ((size_t)bh * SEQ + s) * HDIM;
                dst[ob + d]      = __float2half(x1 * cc - x2 * sn);
                dst[ob + d + 64] = __float2half(x2 * cc + x1 * sn);
            }
        } else {
            size_t vb = (size_t)bh * HDIM * SEQ;
            for (int i = tid; i < 16384; i += 128) {
                int d  = i >> 7;
                int sl = i & 127;
                ovt[vb + (size_t)d * SEQ + s0 + sl] = __float2half(TS[sl * TS_STRIDE + d]);
            }
        }
    }
}

// ============================ HMMA flash attention (fp16, unchanged) =======
#define AT_QROW 272
#define AT_VROW 144
#define AT_Q 0
#define AT_K 34816
#define AT_V 52224
#define ATTN_SMEM 70656

__global__ void __launch_bounds__(256, 2)
attn_kernel(const __half* __restrict__ q, const __half* __restrict__ k,
            const __half* __restrict__ vt, __half* __restrict__ outp)
{
    extern __shared__ __align__(16) char sm[];
    const uint32_t sb = smem_to_u32(sm);

    const int tid  = threadIdx.x;
    const int lane = tid & 31;
    const int w    = tid >> 5;
    const int bh   = blockIdx.y;
    const int b    = bh >> 5;
    const int h    = bh & 31;
    const int q0   = blockIdx.x * 128;
    const size_t hoff  = (size_t)bh * SEQ * HDIM;
    const size_t vbase = (size_t)bh * HDIM * SEQ;

    const uint32_t a_lane  = (uint32_t)(lane & 15) * AT_QROW + (uint32_t)(lane >> 4) * 16;
    const uint32_t b_row   = (uint32_t)((lane & 7) | ((lane >> 4) << 3));
    const uint32_t bk_lane = b_row * AT_QROW + (uint32_t)((lane >> 3) & 1) * 16;
    const uint32_t bv_lane = b_row * AT_VROW + (uint32_t)((lane >> 3) & 1) * 16;

    for (int i = tid; i < 2048; i += 256) {
        int r = i >> 4, c = i & 15;
        uint4 v = *(const uint4*)(q + hoff + (size_t)(q0 + r) * HDIM + c * 8);
        *(uint4*)(sm + AT_Q + r * AT_QROW + c * 16) = v;
    }

    const int g = lane >> 2;
    const int qq0 = q0 + w * 16 + g;
    const int qq1 = qq0 + 8;
    const int wrow_lo = q0 + w * 16;
    const int wrow_hi = wrow_lo + 15;
    const float scale = 0.08838834764831845f;

    float oa[16][4];
#pragma unroll
    for (int i = 0; i < 16; i++)
#pragma unroll
        for (int r = 0; r < 4; r++) oa[i][r] = 0.f;
    float m0 = -1e30f, m1 = -1e30f, l0 = 0.f, l1 = 0.f;

    const int ktmax = 2 * blockIdx.x + 1;
    for (int kt = 0; kt <= ktmax; kt++) {
        const int k0 = kt * 64;
        __syncthreads();
        for (int i = tid; i < 2048; i += 256) {
            if (i < 1024) {
                int r = i >> 4, c = i & 15;
                uint4 v = *(const uint4*)(k + hoff + (size_t)(k0 + r) * HDIM + c * 8);
                *(uint4*)(sm + AT_K + r * AT_QROW + c * 16) = v;
            } else {
                int i2 = i - 1024;
                int r = i2 >> 3, c = i2 & 7;
                uint4 v = *(const uint4*)(vt + vbase + (size_t)r * SEQ + k0 + c * 8);
                *(uint4*)(sm + AT_V + r * AT_VROW + c * 16) = v;
            }
        }
        __syncthreads();

        if (k0 > wrow_hi) continue;

        float sc[8][4];
#pragma unroll
        for (int j = 0; j < 8; j++)
#pragma unroll
            for (int r = 0; r < 4; r++) sc[j][r] = 0.f;

#pragma unroll
        for (int ks = 0; ks < 8; ks++) {
            const uint32_t kb = (uint32_t)ks * 32;
            uint32_t qa[4], kf[4][4];
            ldmatrix_x4(qa[0], qa[1], qa[2], qa[3],
                        sb + AT_Q + (uint32_t)(w * 16) * AT_QROW + kb + a_lane);
#pragma unroll
            for (int j2 = 0; j2 < 4; j2++)
                ldmatrix_x4(kf[j2][0], kf[j2][1], kf[j2][2], kf[j2][3],
                            sb + AT_K + (uint32_t)(j2 * 16) * AT_QROW + kb + bk_lane);
#pragma unroll
            for (int j = 0; j < 8; j++)
                mma_fp16(sc[j], qa, kf[j >> 1][(j & 1) * 2], kf[j >> 1][(j & 1) * 2 + 1]);
        }

        if (k0 + 63 > wrow_lo) {
#pragma unroll
            for (int j = 0; j < 8; j++) {
                int c0 = k0 + j * 8 + (lane & 3) * 2;
                sc[j][0] = sc[j][0] * scale + ((c0     <= qq0) ? 0.f : -1e9f);
                sc[j][1] = sc[j][1] * scale + ((c0 + 1 <= qq0) ? 0.f : -1e9f);
                sc[j][2] = sc[j][2] * scale + ((c0     <= qq1) ? 0.f : -1e9f);
                sc[j][3] = sc[j][3] * scale + ((c0 + 1 <= qq1) ? 0.f : -1e9f);
            }
        } else {
#pragma unroll
            for (int j = 0; j < 8; j++)
#pragma unroll
                for (int r = 0; r < 4; r++) sc[j][r] *= scale;
        }

        float mx0 = -1e30f, mx1 = -1e30f;
#pragma unroll
        for (int j = 0; j < 8; j++) {
            mx0 = fmaxf(mx0, fmaxf(sc[j][0], sc[j][1]));
            mx1 = fmaxf(mx1, fmaxf(sc[j][2], sc[j][3]));
        }
        mx0 = fmaxf(mx0, __shfl_xor_sync(0xffffffffu, mx0, 1));
        mx0 = fmaxf(mx0, __shfl_xor_sync(0xffffffffu, mx0, 2));
        mx1 = fmaxf(mx1, __shfl_xor_sync(0xffffffffu, mx1, 1));
        mx1 = fmaxf(mx1, __shfl_xor_sync(0xffffffffu, mx1, 2));
        float mn0 = fmaxf(m0, mx0), mn1 = fmaxf(m1, mx1);
        float al0 = __expf(m0 - mn0), al1 = __expf(m1 - mn1);

        float s0 = 0.f, s1 = 0.f;
#pragma unroll
        for (int j = 0; j < 8; j++) {
            sc[j][0] = __expf(sc[j][0] - mn0); s0 += sc[j][0];
            sc[j][1] = __expf(sc[j][1] - mn0); s0 += sc[j][1];
            sc[j][2] = __expf(sc[j][2] - mn1); s1 += sc[j][2];
            sc[j][3] = __expf(sc[j][3] - mn1); s1 += sc[j][3];
        }
        s0 += __shfl_xor_sync(0xffffffffu, s0, 1);
        s0 += __shfl_xor_sync(0xffffffffu, s0, 2);
        s1 += __shfl_xor_sync(0xffffffffu, s1, 1);
        s1 += __shfl_xor_sync(0xffffffffu, s1, 2);
        l0 = l0 * al0 + s0; m0 = mn0;
        l1 = l1 * al1 + s1; m1 = mn1;

#pragma unroll
        for (int i = 0; i < 16; i++) {
            oa[i][0] *= al0; oa[i][1] *= al0;
            oa[i][2] *= al1; oa[i][3] *= al1;
        }

        uint32_t pf[4][4];
#pragma unroll
        for (int t = 0; t < 4; t++) {
            int j = 2 * t;
            pf[t][0] = pack_half2(sc[j][0],     sc[j][1]);
            pf[t][1] = pack_half2(sc[j][2],     sc[j][3]);
            pf[t][2] = pack_half2(sc[j + 1][0], sc[j + 1][1]);
            pf[t][3] = pack_half2(sc[j + 1][2], sc[j + 1][3]);
        }

#pragma unroll
        for (int t = 0; t < 4; t++) {
            const uint32_t kb = (uint32_t)t * 32;
#pragma unroll
            for (int n2 = 0; n2 < 8; n2++) {
                uint32_t vf[4];
                ldmatrix_x4(vf[0], vf[1], vf[2], vf[3],
                            sb + AT_V + (uint32_t)(n2 * 16) * AT_VROW + kb + bv_lane);
#pragma unroll
                for (int qh = 0; qh < 2; qh++)
                    mma_fp16(oa[n2 * 2 + qh], pf[t], vf[qh * 2], vf[qh * 2 + 1]);
            }
        }
    }

    float il0 = 1.f / l0, il1 = 1.f / l1;
    size_t base0 = ((size_t)(b * SEQ + qq0)) * HID + (size_t)h * HDIM;
    size_t base1 = ((size_t)(b * SEQ + qq1)) * HID + (size_t)h * HDIM;
#pragma unroll
    for (int nt = 0; nt < 16; nt++) {
        int d = nt * 8 + (lane & 3) * 2;
        *(uint32_t*)(outp + base0 + d) = pack_half2(oa[nt][0] * il0, oa[nt][1] * il0);
        *(uint32_t*)(outp + base1 + d) = pack_half2(oa[nt][2] * il1, oa[nt][3] * il1);
    }
}

// ============================ launch =======================================
extern "C" void kernel_launch(void* const* d_in, const int* in_sizes, int n_in,
                              void* d_out, int out_size)
{
    const float* hidden = (const float*)d_in[0];
    const float* Wp     = (const float*)d_in[1];
    const float* Wo     = (const float*)d_in[2];
    float* out = (float*)d_out;

    __half *a1, *bp, *bo, *at, *qh, *kh, *vth;
    cudaGetSymbolAddress((void**)&a1,  g_a1);
    cudaGetSymbolAddress((void**)&bp,  g_bp);
    cudaGetSymbolAddress((void**)&bo,  g_bo);
    cudaGetSymbolAddress((void**)&at,  g_at);
    cudaGetSymbolAddress((void**)&qh,  g_q);
    cudaGetSymbolAddress((void**)&kh,  g_k);
    cudaGetSymbolAddress((void**)&vth, g_vt);

    // Prep: convert hidden; transpose+convert weights
    convert_kernel<<<(M_ROWS * KDIM / 4 + 255) / 256, 256>>>(hidden, a1, M_ROWS * KDIM / 4);
    transpose_convert_kernel<<<dim3(QKV_N / 32, KDIM / 32), dim3(32, 8)>>>(Wp, bp, KDIM, QKV_N);
    transpose_convert_kernel<<<dim3(HID  / 32, KDIM / 32), dim3(32, 8)>>>(Wo, bo, KDIM, HID);

    cudaFuncSetAttribute(hmma_gemm_kernel<0>, cudaFuncAttributeMaxDynamicSharedMemorySize, GEMM_SMEM);
    cudaFuncSetAttribute(hmma_gemm_kernel<1>, cudaFuncAttributeMaxDynamicSharedMemorySize, GEMM_SMEM);
    cudaFuncSetAttribute(attn_kernel, cudaFuncAttributeMaxDynamicSharedMemorySize, ATTN_SMEM);

    // GEMM1: QKV projection with fused RoPE / V-transpose epilogue
    hmma_gemm_kernel<1><<<dim3(QKV_N / 128, M_ROWS / 128), 128, GEMM_SMEM>>>(
        a1, bp, nullptr, qh, kh, vth);

    // Flash attention (HMMA fp16, BM=128)
    attn_kernel<<<dim3(SEQ / 128, BATCH * NHEAD), 256, ATTN_SMEM>>>(
        qh, kh, vth, at);

    // GEMM2: output projection
    hmma_gemm_kernel<0><<<dim3(HID / 128, M_ROWS / 128), 128, GEMM_SMEM>>>(
        at, bo, out, nullptr, nullptr, nullptr);
}